// round 2
// baseline (speedup 1.0000x reference)
#include <cuda_runtime.h>
#include <math.h>

#define B_DIM 4
#define T_DIM 2048
#define S_DIM 2048
#define C_DIM 1024
#define H_DIM 16
#define D_DIM 64

// Scratch for projected q, k, v (allocation-free: __device__ globals).
__device__ float g_q[(size_t)B_DIM * T_DIM * C_DIM];
__device__ float g_k[(size_t)B_DIM * S_DIM * C_DIM];
__device__ float g_v[(size_t)B_DIM * S_DIM * C_DIM];

// ---------------------------------------------------------------------------
// Projection GEMM: out[m][n] = sum_k A[m][k] * W[n][k] + bias[n]
// M=8192, N=1024, K=1024.  BM=BN=128, BK=16, 256 threads, 8x8 per thread
// (split-tile: two float4 fragments 64 apart -> conflict-free LDS.128).
// ---------------------------------------------------------------------------
__global__ __launch_bounds__(256)
void proj_gemm(const float* __restrict__ A,
               const float* __restrict__ W,
               const float* __restrict__ bias,
               float* __restrict__ out,
               int M, int N, int K) {
    __shared__ float As[16][128];
    __shared__ float Ws[16][128];

    const int tid = threadIdx.x;
    const int tr  = tid >> 4;    // 0..15 (row group)
    const int tc  = tid & 15;    // 0..15 (col group)
    const int bm  = blockIdx.y << 7;
    const int bn  = blockIdx.x << 7;

    float acc[2][4][2][4];
#pragma unroll
    for (int im = 0; im < 2; im++)
#pragma unroll
        for (int i = 0; i < 4; i++)
#pragma unroll
            for (int jm = 0; jm < 2; jm++)
#pragma unroll
                for (int j = 0; j < 4; j++) acc[im][i][jm][j] = 0.f;

    for (int k0 = 0; k0 < K; k0 += 16) {
#pragma unroll
        for (int it = 0; it < 2; it++) {
            int idx = tid + (it << 8);      // 0..511
            int r   = idx >> 2;             // 0..127
            int c4  = (idx & 3) << 2;       // 0,4,8,12
            float4 av = *(const float4*)(A + (size_t)(bm + r) * K + k0 + c4);
            As[c4 + 0][r] = av.x; As[c4 + 1][r] = av.y;
            As[c4 + 2][r] = av.z; As[c4 + 3][r] = av.w;
            float4 wv = *(const float4*)(W + (size_t)(bn + r) * K + k0 + c4);
            Ws[c4 + 0][r] = wv.x; Ws[c4 + 1][r] = wv.y;
            Ws[c4 + 2][r] = wv.z; Ws[c4 + 3][r] = wv.w;
        }
        __syncthreads();

#pragma unroll
        for (int kk = 0; kk < 16; kk++) {
            float4 a0 = *(const float4*)&As[kk][tr << 2];
            float4 a1 = *(const float4*)&As[kk][64 + (tr << 2)];
            float4 w0 = *(const float4*)&Ws[kk][tc << 2];
            float4 w1 = *(const float4*)&Ws[kk][64 + (tc << 2)];
            float aa[2][4] = {{a0.x, a0.y, a0.z, a0.w}, {a1.x, a1.y, a1.z, a1.w}};
            float ww[2][4] = {{w0.x, w0.y, w0.z, w0.w}, {w1.x, w1.y, w1.z, w1.w}};
#pragma unroll
            for (int im = 0; im < 2; im++)
#pragma unroll
                for (int i = 0; i < 4; i++)
#pragma unroll
                    for (int jm = 0; jm < 2; jm++)
#pragma unroll
                        for (int j = 0; j < 4; j++)
                            acc[im][i][jm][j] += aa[im][i] * ww[jm][j];
        }
        __syncthreads();
    }

#pragma unroll
    for (int im = 0; im < 2; im++)
#pragma unroll
        for (int i = 0; i < 4; i++) {
            int row = bm + im * 64 + (tr << 2) + i;
#pragma unroll
            for (int jm = 0; jm < 2; jm++) {
                int col = bn + jm * 64 + (tc << 2);
                float4 bv = *(const float4*)(bias + col);
                float4 o;
                o.x = acc[im][i][jm][0] + bv.x;
                o.y = acc[im][i][jm][1] + bv.y;
                o.z = acc[im][i][jm][2] + bv.z;
                o.w = acc[im][i][jm][3] + bv.w;
                *(float4*)(out + (size_t)row * N + col) = o;
            }
        }
}

// ---------------------------------------------------------------------------
// Flash attention: one CTA per (b, h, 64 Q rows).  S processed in 64 chunks.
// Q/K smem layout: d-major [d][r] with XOR-4 column swizzle ->
// conflict-free float4 compute loads.  P aliases K buffer (48KB total smem).
// Online softmax across the 16 tx lanes (width-16 shuffles).
// ---------------------------------------------------------------------------
__global__ __launch_bounds__(256)
void attn_kernel(const float* __restrict__ qg,
                 const float* __restrict__ kg,
                 const float* __restrict__ vg,
                 const bool*  __restrict__ maskg,
                 float* __restrict__ outg) {
    __shared__ float Qst[64 * 64];   // [d][r swizzled]
    __shared__ float KPst[64 * 64];  // K: [d][c swizzled] -> later P: [s][r swizzled]
    __shared__ float Vs[64 * 64];    // [s][d] natural

    const int tid = threadIdx.x;
    const int ty  = tid >> 4;   // 0..15 : row group (rows 4*ty..4*ty+3)
    const int tx  = tid & 15;   // 0..15 : col group
    const int b   = blockIdx.z;
    const int h   = blockIdx.y;
    const int t0  = blockIdx.x << 6;

    const float* qb = qg + ((size_t)b * T_DIM + t0) * C_DIM + h * D_DIM;
    const float* kb = kg + (size_t)b * S_DIM * C_DIM + h * D_DIM;
    const float* vb = vg + (size_t)b * S_DIM * C_DIM + h * D_DIM;
    const bool*  mb = maskg + (size_t)b * S_DIM;

    // Load Q tile, scaled by 1/sqrt(D)=0.125, transposed + swizzled.
#pragma unroll
    for (int it = 0; it < 4; it++) {
        int idx = tid + (it << 8);      // 0..1023 float4s
        int r   = idx >> 4;             // 0..63
        int d0  = (idx & 15) << 2;      // 0,4,...,60
        float4 qv = *(const float4*)(qb + (size_t)r * C_DIM + d0);
        int rp = r ^ d0;                // swizzle: bits[2:5] of r XOR (d>>2)
        Qst[(d0 + 0) * 64 + rp] = qv.x * 0.125f;
        Qst[(d0 + 1) * 64 + rp] = qv.y * 0.125f;
        Qst[(d0 + 2) * 64 + rp] = qv.z * 0.125f;
        Qst[(d0 + 3) * 64 + rp] = qv.w * 0.125f;
    }

    float m_i[4], l_i[4], O[4][4];
#pragma unroll
    for (int i = 0; i < 4; i++) {
        m_i[i] = -1e30f;
        l_i[i] = 0.f;
#pragma unroll
        for (int j = 0; j < 4; j++) O[i][j] = 0.f;
    }

    for (int s0 = 0; s0 < S_DIM; s0 += 64) {
        __syncthreads();  // prior PV reads (KPst as P, Vs) complete
        // Load K chunk (transposed+swizzled) and V chunk (natural).
#pragma unroll
        for (int it = 0; it < 4; it++) {
            int idx = tid + (it << 8);
            int r   = idx >> 4;
            int d0  = (idx & 15) << 2;
            float4 kv = *(const float4*)(kb + (size_t)(s0 + r) * C_DIM + d0);
            int rp = r ^ d0;
            KPst[(d0 + 0) * 64 + rp] = kv.x;
            KPst[(d0 + 1) * 64 + rp] = kv.y;
            KPst[(d0 + 2) * 64 + rp] = kv.z;
            KPst[(d0 + 3) * 64 + rp] = kv.w;
            float4 vv = *(const float4*)(vb + (size_t)(s0 + r) * C_DIM + d0);
            *(float4*)&Vs[r * 64 + d0] = vv;
        }
        bool mk[4];
#pragma unroll
        for (int j = 0; j < 4; j++) mk[j] = mb[s0 + (tx << 2) + j];
        __syncthreads();

        // S = Q K^T  (64x64 tile, 4x4 per thread)
        float sc[4][4];
#pragma unroll
        for (int i = 0; i < 4; i++)
#pragma unroll
            for (int j = 0; j < 4; j++) sc[i][j] = 0.f;

#pragma unroll 16
        for (int d = 0; d < 64; d++) {
            int sw = d & 60;
            float4 q4 = *(const float4*)&Qst[d * 64 + ((ty << 2) ^ sw)];
            float4 k4 = *(const float4*)&KPst[d * 64 + ((tx << 2) ^ sw)];
            float qa[4] = {q4.x, q4.y, q4.z, q4.w};
            float ka[4] = {k4.x, k4.y, k4.z, k4.w};
#pragma unroll
            for (int i = 0; i < 4; i++)
#pragma unroll
                for (int j = 0; j < 4; j++) sc[i][j] += qa[i] * ka[j];
        }

#pragma unroll
        for (int j = 0; j < 4; j++)
            if (mk[j]) {
                sc[0][j] = -1e30f; sc[1][j] = -1e30f;
                sc[2][j] = -1e30f; sc[3][j] = -1e30f;
            }

        // Online softmax per row (reduce across 16 tx lanes, width-16 shuffles)
#pragma unroll
        for (int i = 0; i < 4; i++) {
            float rmax = fmaxf(fmaxf(sc[i][0], sc[i][1]), fmaxf(sc[i][2], sc[i][3]));
            rmax = fmaxf(rmax, __shfl_xor_sync(0xffffffffu, rmax, 1, 16));
            rmax = fmaxf(rmax, __shfl_xor_sync(0xffffffffu, rmax, 2, 16));
            rmax = fmaxf(rmax, __shfl_xor_sync(0xffffffffu, rmax, 4, 16));
            rmax = fmaxf(rmax, __shfl_xor_sync(0xffffffffu, rmax, 8, 16));
            float mnew = fmaxf(m_i[i], rmax);
            float corr = __expf(m_i[i] - mnew);
            m_i[i] = mnew;
            float rs = 0.f;
#pragma unroll
            for (int j = 0; j < 4; j++) {
                float p = __expf(sc[i][j] - mnew);
                sc[i][j] = p;
                rs += p;
            }
            rs += __shfl_xor_sync(0xffffffffu, rs, 1, 16);
            rs += __shfl_xor_sync(0xffffffffu, rs, 2, 16);
            rs += __shfl_xor_sync(0xffffffffu, rs, 4, 16);
            rs += __shfl_xor_sync(0xffffffffu, rs, 8, 16);
            l_i[i] = l_i[i] * corr + rs;
#pragma unroll
            for (int jd = 0; jd < 4; jd++) O[i][jd] *= corr;
        }

        __syncthreads();  // everyone done reading KPst as K
        // Write P into KPst: layout [s][r swizzled]
#pragma unroll
        for (int j = 0; j < 4; j++) {
            int sp = (tx << 2) + j;
            *(float4*)&KPst[sp * 64 + ((ty << 2) ^ (sp & 60))] =
                make_float4(sc[0][j], sc[1][j], sc[2][j], sc[3][j]);
        }
        __syncthreads();  // P ready

        // O += P @ V
#pragma unroll 8
        for (int s = 0; s < 64; s++) {
            float4 p4 = *(const float4*)&KPst[s * 64 + ((ty << 2) ^ (s & 60))];
            float4 v4 = *(const float4*)&Vs[s * 64 + (tx << 2)];
            float pa[4] = {p4.x, p4.y, p4.z, p4.w};
            float va[4] = {v4.x, v4.y, v4.z, v4.w};
#pragma unroll
            for (int i = 0; i < 4; i++)
#pragma unroll
                for (int jd = 0; jd < 4; jd++) O[i][jd] += pa[i] * va[jd];
        }
    }

    // Finalize: out[b, t0+row, h*D + dim] = O / l
#pragma unroll
    for (int i = 0; i < 4; i++) {
        float inv = 1.0f / l_i[i];
        int row = t0 + (ty << 2) + i;
        float4 o = make_float4(O[i][0] * inv, O[i][1] * inv,
                               O[i][2] * inv, O[i][3] * inv);
        *(float4*)(outg + ((size_t)b * T_DIM + row) * C_DIM + h * D_DIM + (tx << 2)) = o;
    }
}

extern "C" void kernel_launch(void* const* d_in, const int* in_sizes, int n_in,
                              void* d_out, int out_size) {
    const float* query = (const float*)d_in[0];
    const float* key   = (const float*)d_in[1];
    const float* value = (const float*)d_in[2];
    const bool*  kmask = (const bool*)d_in[3];
    const float* Wq = (const float*)d_in[4];
    const float* bq = (const float*)d_in[5];
    const float* Wk = (const float*)d_in[6];
    const float* bk = (const float*)d_in[7];
    const float* Wv = (const float*)d_in[8];
    const float* bv = (const float*)d_in[9];
    float* out = (float*)d_out;

    float *qp = nullptr, *kp = nullptr, *vp = nullptr;
    cudaGetSymbolAddress((void**)&qp, g_q);
    cudaGetSymbolAddress((void**)&kp, g_k);
    cudaGetSymbolAddress((void**)&vp, g_v);

    const int M = B_DIM * T_DIM;          // 8192
    const int N = C_DIM, K = C_DIM;       // 1024
    dim3 gg(N / 128, M / 128);            // (8, 64)
    proj_gemm<<<gg, 256>>>(query, Wq, bq, qp, M, N, K);
    proj_gemm<<<gg, 256>>>(key,   Wk, bk, kp, M, N, K);
    proj_gemm<<<gg, 256>>>(value, Wv, bv, vp, M, N, K);

    dim3 ga(T_DIM / 64, H_DIM, B_DIM);    // (32, 16, 4)
    attn_kernel<<<ga, 256>>>(qp, kp, vp, kmask, out);
}

// round 3
// speedup vs baseline: 2.7681x; 2.7681x over previous
#include <cuda_runtime.h>
#include <math.h>

#define B_DIM 4
#define T_DIM 2048
#define S_DIM 2048
#define C_DIM 1024
#define H_DIM 16
#define D_DIM 64

// Scratch for projected q, k, v (allocation-free: __device__ globals).
__device__ float g_q[(size_t)B_DIM * T_DIM * C_DIM];
__device__ float g_k[(size_t)B_DIM * S_DIM * C_DIM];
__device__ float g_v[(size_t)B_DIM * S_DIM * C_DIM];

__device__ __forceinline__ unsigned f2tf(float x) {
    unsigned u;
    asm("cvt.rna.tf32.f32 %0, %1;" : "=r"(u) : "f"(x));
    return u;
}

__device__ __forceinline__ void mma_tf32(float c[4],
                                         unsigned a0, unsigned a1, unsigned a2, unsigned a3,
                                         unsigned b0, unsigned b1) {
    asm volatile(
        "mma.sync.aligned.m16n8k8.row.col.f32.tf32.tf32.f32 "
        "{%0,%1,%2,%3}, {%4,%5,%6,%7}, {%8,%9}, {%0,%1,%2,%3};"
        : "+f"(c[0]), "+f"(c[1]), "+f"(c[2]), "+f"(c[3])
        : "r"(a0), "r"(a1), "r"(a2), "r"(a3), "r"(b0), "r"(b1));
}

// ---------------------------------------------------------------------------
// QKV projection GEMM (z-batched over q/k/v):
//   out[m][n] = sum_k A[m][k] * W[n][k] + bias[n],  M=8192, N=K=1024.
// Block 128x128, BK=32, 8 warps (2x4), warp tile 64x32, tf32 HMMA.
// smem layout: [row][k ^ 4*(row&7)], stride 32 -> conflict-free frag LDS.
// ---------------------------------------------------------------------------
__global__ __launch_bounds__(256, 2)
void qkv_gemm(const float* __restrict__ Aq, const float* __restrict__ Ak,
              const float* __restrict__ Av,
              const float* __restrict__ Wq, const float* __restrict__ bq,
              const float* __restrict__ Wk, const float* __restrict__ bk,
              const float* __restrict__ Wv, const float* __restrict__ bv,
              float* __restrict__ oq, float* __restrict__ ok_,
              float* __restrict__ ov) {
    __shared__ unsigned As[128 * 32];
    __shared__ unsigned Ws[128 * 32];

    const float* A;
    const float* W;
    const float* bias;
    float* out;
    if (blockIdx.z == 0)      { A = Aq; W = Wq; bias = bq; out = oq; }
    else if (blockIdx.z == 1) { A = Ak; W = Wk; bias = bk; out = ok_; }
    else                      { A = Av; W = Wv; bias = bv; out = ov; }

    const int K = C_DIM, N = C_DIM;
    const int tid  = threadIdx.x;
    const int lane = tid & 31;
    const int w    = tid >> 5;
    const int wm   = w >> 2;    // 0..1
    const int wn   = w & 3;     // 0..3
    const int u    = lane & 3;
    const int qd   = lane >> 2;
    const int swz  = 4 * qd;
    const int bm   = blockIdx.y << 7;
    const int bn   = blockIdx.x << 7;

    float acc[4][4][4];
#pragma unroll
    for (int mf = 0; mf < 4; mf++)
#pragma unroll
        for (int nf = 0; nf < 4; nf++)
#pragma unroll
            for (int e = 0; e < 4; e++) acc[mf][nf][e] = 0.f;

    // prefetch registers (4 float4 per tensor per thread)
    float4 pa[4], pw[4];
#pragma unroll
    for (int i = 0; i < 4; i++) {
        int idx = tid + (i << 8);
        int r   = idx >> 3;
        int c4  = (idx & 7) << 2;
        pa[i] = *(const float4*)(A + (size_t)(bm + r) * K + c4);
        pw[i] = *(const float4*)(W + (size_t)(bn + r) * K + c4);
    }

    for (int k0 = 0; k0 < K; k0 += 32) {
        // store prefetched tile (tf32-rounded), swizzled
#pragma unroll
        for (int i = 0; i < 4; i++) {
            int idx = tid + (i << 8);
            int r   = idx >> 3;
            int c4  = (idx & 7) << 2;
            int o   = r * 32 + (c4 ^ (4 * (r & 7)));
            As[o + 0] = f2tf(pa[i].x); As[o + 1] = f2tf(pa[i].y);
            As[o + 2] = f2tf(pa[i].z); As[o + 3] = f2tf(pa[i].w);
            Ws[o + 0] = f2tf(pw[i].x); Ws[o + 1] = f2tf(pw[i].y);
            Ws[o + 2] = f2tf(pw[i].z); Ws[o + 3] = f2tf(pw[i].w);
        }
        __syncthreads();

        if (k0 + 32 < K) {
#pragma unroll
            for (int i = 0; i < 4; i++) {
                int idx = tid + (i << 8);
                int r   = idx >> 3;
                int c4  = (idx & 7) << 2;
                pa[i] = *(const float4*)(A + (size_t)(bm + r) * K + k0 + 32 + c4);
                pw[i] = *(const float4*)(W + (size_t)(bn + r) * K + k0 + 32 + c4);
            }
        }

#pragma unroll
        for (int kk = 0; kk < 32; kk += 8) {
            int c0 = (kk + u) ^ swz;
            int c1 = c0 ^ 4;
            unsigned af[4][4];
#pragma unroll
            for (int mf = 0; mf < 4; mf++) {
                int r0 = ((wm << 6) + (mf << 4) + qd) << 5;
                af[mf][0] = As[r0 + c0];
                af[mf][1] = As[r0 + 256 + c0];
                af[mf][2] = As[r0 + c1];
                af[mf][3] = As[r0 + 256 + c1];
            }
            unsigned bf[4][2];
#pragma unroll
            for (int nf = 0; nf < 4; nf++) {
                int rn = ((wn << 5) + (nf << 3) + qd) << 5;
                bf[nf][0] = Ws[rn + c0];
                bf[nf][1] = Ws[rn + c1];
            }
#pragma unroll
            for (int mf = 0; mf < 4; mf++)
#pragma unroll
                for (int nf = 0; nf < 4; nf++)
                    mma_tf32(acc[mf][nf], af[mf][0], af[mf][1], af[mf][2], af[mf][3],
                             bf[nf][0], bf[nf][1]);
        }
        __syncthreads();
    }

    // epilogue: add bias, write float2 pairs
#pragma unroll
    for (int mf = 0; mf < 4; mf++) {
        int gr0 = bm + (wm << 6) + (mf << 4) + qd;
#pragma unroll
        for (int nf = 0; nf < 4; nf++) {
            int gc = bn + (wn << 5) + (nf << 3) + (u << 1);
            float2 bz = *(const float2*)(bias + gc);
            float2 o0 = make_float2(acc[mf][nf][0] + bz.x, acc[mf][nf][1] + bz.y);
            float2 o1 = make_float2(acc[mf][nf][2] + bz.x, acc[mf][nf][3] + bz.y);
            *(float2*)(out + (size_t)gr0 * N + gc)       = o0;
            *(float2*)(out + (size_t)(gr0 + 8) * N + gc) = o1;
        }
    }
}

// ---------------------------------------------------------------------------
// Flash attention, tf32 HMMA. CTA = (b, h, 128 q rows), 8 warps, warp = 16
// full rows. S chunk = 64. Q:[t][d], K:[s][d] (native col-major for QK^T),
// V transposed to [d][s], P round-trips through warp-private smem tile.
// All smem rows stride 64 with XOR swizzle col ^ 4*(row&7).
// ---------------------------------------------------------------------------
#define SMEM_Q   0
#define SMEM_K   (128 * 64)
#define SMEM_V   (SMEM_K + 64 * 64)
#define SMEM_P   (SMEM_V + 64 * 64)
#define SMEM_MSK (SMEM_P + 128 * 64)
#define SMEM_ATTN_WORDS (SMEM_MSK + 64)

__global__ __launch_bounds__(256, 2)
void attn_kernel(const float* __restrict__ qg,
                 const float* __restrict__ kg,
                 const float* __restrict__ vg,
                 const bool*  __restrict__ maskg,
                 float* __restrict__ outg) {
    extern __shared__ unsigned sm[];
    unsigned* Qs = sm + SMEM_Q;
    unsigned* Ks = sm + SMEM_K;
    unsigned* Vs = sm + SMEM_V;
    unsigned* Ps = sm + SMEM_P;
    float*    msk = (float*)(sm + SMEM_MSK);

    const int tid  = threadIdx.x;
    const int lane = tid & 31;
    const int w    = tid >> 5;      // 0..7 -> rows 16w..16w+15
    const int u    = lane & 3;
    const int qd   = lane >> 2;     // 0..7
    const int swz  = 4 * qd;
    const int b    = blockIdx.z;
    const int h    = blockIdx.y;
    const int t0   = blockIdx.x << 7;
    const int R0   = w << 4;

    const float* qb = qg + ((size_t)b * T_DIM + t0) * C_DIM + h * D_DIM;
    const float* kb = kg + (size_t)b * S_DIM * C_DIM + h * D_DIM;
    const float* vb = vg + (size_t)b * S_DIM * C_DIM + h * D_DIM;
    const bool*  mb = maskg + (size_t)b * S_DIM;

    // Load Q tile (scaled 1/8, tf32), layout [r][d ^ 4*(r&7)]
#pragma unroll
    for (int i = 0; i < 8; i++) {
        int idx = tid + (i << 8);
        int r   = idx >> 4;
        int d0  = (idx & 15) << 2;
        float4 qv = *(const float4*)(qb + (size_t)r * C_DIM + d0);
        int o = (r << 6) + (d0 ^ (4 * (r & 7)));
        Qs[o + 0] = f2tf(qv.x * 0.125f); Qs[o + 1] = f2tf(qv.y * 0.125f);
        Qs[o + 2] = f2tf(qv.z * 0.125f); Qs[o + 3] = f2tf(qv.w * 0.125f);
    }

    float m0 = -1e30f, m1 = -1e30f, l0 = 0.f, l1 = 0.f;
    float oacc[8][4];
#pragma unroll
    for (int df = 0; df < 8; df++)
#pragma unroll
        for (int e = 0; e < 4; e++) oacc[df][e] = 0.f;

    for (int s0 = 0; s0 < S_DIM; s0 += 64) {
        __syncthreads();  // prior chunk's K/V readers done
        // K chunk: [s][d ^ 4*(s&7)]
#pragma unroll
        for (int i = 0; i < 4; i++) {
            int idx = tid + (i << 8);
            int s   = idx >> 4;
            int d0  = (idx & 15) << 2;
            float4 kv = *(const float4*)(kb + (size_t)(s0 + s) * C_DIM + d0);
            int o = (s << 6) + (d0 ^ (4 * (s & 7)));
            Ks[o + 0] = f2tf(kv.x); Ks[o + 1] = f2tf(kv.y);
            Ks[o + 2] = f2tf(kv.z); Ks[o + 3] = f2tf(kv.w);
        }
        // V chunk transposed: Vs[d][s ^ 4*(d&7)]
#pragma unroll
        for (int i = 0; i < 4; i++) {
            int idx = tid + (i << 8);
            int s   = idx & 63;
            int d0  = ((idx >> 6) & 3) << 2;
            d0 += (i & 0) ; // (kept simple: full coverage below)
            d0 = (((idx >> 6) & 3) << 2) + ((i) << 4);
            // recompute cleanly: i in 0..3 supplies 16-d blocks
            float4 vv = *(const float4*)(vb + (size_t)(s0 + s) * C_DIM + d0);
            Vs[((d0 + 0) << 6) + (s ^ (4 * ((d0 + 0) & 7)))] = f2tf(vv.x);
            Vs[((d0 + 1) << 6) + (s ^ (4 * ((d0 + 1) & 7)))] = f2tf(vv.y);
            Vs[((d0 + 2) << 6) + (s ^ (4 * ((d0 + 2) & 7)))] = f2tf(vv.z);
            Vs[((d0 + 3) << 6) + (s ^ (4 * ((d0 + 3) & 7)))] = f2tf(vv.w);
        }
        if (tid < 64) msk[tid] = mb[s0 + tid] ? -1e30f : 0.f;
        __syncthreads();

        // ---- S = Q K^T (warp: 16 rows x 64 cols) ----
        float sc[8][4];
#pragma unroll
        for (int nf = 0; nf < 8; nf++)
#pragma unroll
            for (int e = 0; e < 4; e++) sc[nf][e] = 0.f;

#pragma unroll
        for (int kk = 0; kk < 64; kk += 8) {
            int c0 = (kk + u) ^ swz;
            int c1 = c0 ^ 4;
            int ra = (R0 + qd) << 6;
            unsigned a0 = Qs[ra + c0];
            unsigned a1 = Qs[ra + 512 + c0];   // +8 rows * 64
            unsigned a2 = Qs[ra + c1];
            unsigned a3 = Qs[ra + 512 + c1];
#pragma unroll
            for (int nf = 0; nf < 8; nf++) {
                int rb = ((nf << 3) + qd) << 6;
                mma_tf32(sc[nf], a0, a1, a2, a3, Ks[rb + c0], Ks[rb + c1]);
            }
        }

        // mask bias
#pragma unroll
        for (int nf = 0; nf < 8; nf++) {
            float bm0 = msk[(nf << 3) + (u << 1)];
            float bm1 = msk[(nf << 3) + (u << 1) + 1];
            sc[nf][0] += bm0; sc[nf][1] += bm1;
            sc[nf][2] += bm0; sc[nf][3] += bm1;
        }

        // ---- online softmax (rows qd and qd+8 of warp tile) ----
        float mx0 = -1e30f, mx1 = -1e30f;
#pragma unroll
        for (int nf = 0; nf < 8; nf++) {
            mx0 = fmaxf(mx0, fmaxf(sc[nf][0], sc[nf][1]));
            mx1 = fmaxf(mx1, fmaxf(sc[nf][2], sc[nf][3]));
        }
        mx0 = fmaxf(mx0, __shfl_xor_sync(0xffffffffu, mx0, 1));
        mx0 = fmaxf(mx0, __shfl_xor_sync(0xffffffffu, mx0, 2));
        mx1 = fmaxf(mx1, __shfl_xor_sync(0xffffffffu, mx1, 1));
        mx1 = fmaxf(mx1, __shfl_xor_sync(0xffffffffu, mx1, 2));

        float mn0 = fmaxf(m0, mx0), mn1 = fmaxf(m1, mx1);
        float cr0 = __expf(m0 - mn0), cr1 = __expf(m1 - mn1);
        m0 = mn0; m1 = mn1;

        float sum0 = 0.f, sum1 = 0.f;
        int pr0 = (R0 + qd) << 6;
        int pr1 = pr0 + 512;
#pragma unroll
        for (int nf = 0; nf < 8; nf++) {
            float p0 = __expf(sc[nf][0] - mn0);
            float p1 = __expf(sc[nf][1] - mn0);
            float p2 = __expf(sc[nf][2] - mn1);
            float p3 = __expf(sc[nf][3] - mn1);
            sum0 += p0 + p1; sum1 += p2 + p3;
            int pc = ((nf << 3) + (u << 1)) ^ swz;
            uint2 w0; w0.x = f2tf(p0); w0.y = f2tf(p1);
            uint2 w1; w1.x = f2tf(p2); w1.y = f2tf(p3);
            *(uint2*)&Ps[pr0 + pc] = w0;
            *(uint2*)&Ps[pr1 + pc] = w1;
        }
        sum0 += __shfl_xor_sync(0xffffffffu, sum0, 1);
        sum0 += __shfl_xor_sync(0xffffffffu, sum0, 2);
        sum1 += __shfl_xor_sync(0xffffffffu, sum1, 1);
        sum1 += __shfl_xor_sync(0xffffffffu, sum1, 2);
        l0 = l0 * cr0 + sum0;
        l1 = l1 * cr1 + sum1;
#pragma unroll
        for (int df = 0; df < 8; df++) {
            oacc[df][0] *= cr0; oacc[df][1] *= cr0;
            oacc[df][2] *= cr1; oacc[df][3] *= cr1;
        }
        __syncwarp();  // P tile is warp-private: warp-level sync suffices

        // ---- O += P V ----
#pragma unroll
        for (int kk = 0; kk < 64; kk += 8) {
            int c0 = (kk + u) ^ swz;
            int c1 = c0 ^ 4;
            unsigned a0 = Ps[pr0 + c0];
            unsigned a1 = Ps[pr1 + c0];
            unsigned a2 = Ps[pr0 + c1];
            unsigned a3 = Ps[pr1 + c1];
#pragma unroll
            for (int df = 0; df < 8; df++) {
                int rb = ((df << 3) + qd) << 6;
                mma_tf32(oacc[df], a0, a1, a2, a3, Vs[rb + c0], Vs[rb + c1]);
            }
        }
    }

    // finalize
    float inv0 = 1.0f / l0, inv1 = 1.0f / l1;
    int gr0 = t0 + R0 + qd;
#pragma unroll
    for (int df = 0; df < 8; df++) {
        int gc = h * D_DIM + (df << 3) + (u << 1);
        float2 o0 = make_float2(oacc[df][0] * inv0, oacc[df][1] * inv0);
        float2 o1 = make_float2(oacc[df][2] * inv1, oacc[df][3] * inv1);
        *(float2*)(outg + ((size_t)b * T_DIM + gr0) * C_DIM + gc)     = o0;
        *(float2*)(outg + ((size_t)b * T_DIM + gr0 + 8) * C_DIM + gc) = o1;
    }
}

extern "C" void kernel_launch(void* const* d_in, const int* in_sizes, int n_in,
                              void* d_out, int out_size) {
    const float* query = (const float*)d_in[0];
    const float* key   = (const float*)d_in[1];
    const float* value = (const float*)d_in[2];
    const bool*  kmask = (const bool*)d_in[3];
    const float* Wq = (const float*)d_in[4];
    const float* bq = (const float*)d_in[5];
    const float* Wk = (const float*)d_in[6];
    const float* bk = (const float*)d_in[7];
    const float* Wv = (const float*)d_in[8];
    const float* bv = (const float*)d_in[9];
    float* out = (float*)d_out;

    float *qp = nullptr, *kp = nullptr, *vp = nullptr;
    cudaGetSymbolAddress((void**)&qp, g_q);
    cudaGetSymbolAddress((void**)&kp, g_k);
    cudaGetSymbolAddress((void**)&vp, g_v);

    dim3 gg(C_DIM / 128, (B_DIM * T_DIM) / 128, 3);   // (8, 64, 3)
    qkv_gemm<<<gg, 256>>>(query, key, value, Wq, bq, Wk, bk, Wv, bv, qp, kp, vp);

    static int smem_set = 0;
    if (!smem_set) {
        cudaFuncSetAttribute(attn_kernel, cudaFuncAttributeMaxDynamicSharedMemorySize,
                             SMEM_ATTN_WORDS * sizeof(unsigned));
        smem_set = 1;
    }
    dim3 ga(T_DIM / 128, H_DIM, B_DIM);               // (16, 16, 4)
    attn_kernel<<<ga, 256, SMEM_ATTN_WORDS * sizeof(unsigned)>>>(qp, kp, vp, kmask, out);
}

// round 4
// speedup vs baseline: 2.8132x; 1.0163x over previous
#include <cuda_runtime.h>
#include <math.h>

#define B_DIM 4
#define T_DIM 2048
#define S_DIM 2048
#define C_DIM 1024
#define H_DIM 16
#define D_DIM 64

__device__ float g_q[(size_t)B_DIM * T_DIM * C_DIM];
__device__ float g_k[(size_t)B_DIM * S_DIM * C_DIM];
__device__ float g_v[(size_t)B_DIM * S_DIM * C_DIM];

__device__ __forceinline__ unsigned f2tf(float x) {
    unsigned u;
    asm("cvt.rna.tf32.f32 %0, %1;" : "=r"(u) : "f"(x));
    return u;
}

__device__ __forceinline__ void mma_tf32(float c[4],
                                         unsigned a0, unsigned a1, unsigned a2, unsigned a3,
                                         unsigned b0, unsigned b1) {
    asm volatile(
        "mma.sync.aligned.m16n8k8.row.col.f32.tf32.tf32.f32 "
        "{%0,%1,%2,%3}, {%4,%5,%6,%7}, {%8,%9}, {%0,%1,%2,%3};"
        : "+f"(c[0]), "+f"(c[1]), "+f"(c[2]), "+f"(c[3])
        : "r"(a0), "r"(a1), "r"(a2), "r"(a3), "r"(b0), "r"(b1));
}

__device__ __forceinline__ void cp16(float* s, const float* g) {
    unsigned sa = (unsigned)__cvta_generic_to_shared(s);
    asm volatile("cp.async.ca.shared.global [%0], [%1], 16;" :: "r"(sa), "l"(g));
}
#define CP_COMMIT() asm volatile("cp.async.commit_group;")
#define CP_WAIT0()  asm volatile("cp.async.wait_group 0;")

// ---------------------------------------------------------------------------
// QKV projection GEMM (z-batched): out[m][n] = sum_k A[m][k]*W[n][k] + b[n]
// Block tile 256x128, BK=32, 8 warps (4x2), warp tile 64x64 (1.0 LDS/mma).
// cp.async double-buffered smem (raw fp32), tf32 cvt on fragment load.
// smem row layout: [row][c ^ 4*(row&7)], stride 32.
// ---------------------------------------------------------------------------
#define G_STAGE 12288   // 256*32 + 128*32 floats
__global__ __launch_bounds__(256)
void qkv_gemm(const float* __restrict__ Aq, const float* __restrict__ Ak,
              const float* __restrict__ Av,
              const float* __restrict__ Wq, const float* __restrict__ bq,
              const float* __restrict__ Wk, const float* __restrict__ bk,
              const float* __restrict__ Wv, const float* __restrict__ bv,
              float* __restrict__ oq, float* __restrict__ ok_,
              float* __restrict__ ov) {
    extern __shared__ float smg[];

    const float* A; const float* W; const float* bias; float* out;
    if (blockIdx.z == 0)      { A = Aq; W = Wq; bias = bq; out = oq; }
    else if (blockIdx.z == 1) { A = Ak; W = Wk; bias = bk; out = ok_; }
    else                      { A = Av; W = Wv; bias = bv; out = ov; }

    const int tid  = threadIdx.x;
    const int lane = tid & 31;
    const int w    = tid >> 5;
    const int wm   = w & 3;     // 0..3 rows
    const int wn   = w >> 2;    // 0..1 cols
    const int u    = lane & 3;
    const int qd   = lane >> 2;
    const int swz  = 4 * qd;
    const int bm   = blockIdx.y << 8;   // 256-row tile
    const int bn   = blockIdx.x << 7;   // 128-col tile

    float acc[4][8][4];
#pragma unroll
    for (int mf = 0; mf < 4; mf++)
#pragma unroll
        for (int nf = 0; nf < 8; nf++)
#pragma unroll
            for (int e = 0; e < 4; e++) acc[mf][nf][e] = 0.f;

    // issue tile 0
    {
        float* sA = smg; float* sW = smg + 8192;
#pragma unroll
        for (int i = 0; i < 8; i++) {
            int idx = tid + (i << 8);
            int r = idx >> 3, c4 = (idx & 7) << 2;
            cp16(sA + r * 32 + (c4 ^ (4 * (r & 7))),
                 A + (size_t)(bm + r) * C_DIM + c4);
        }
#pragma unroll
        for (int i = 0; i < 4; i++) {
            int idx = tid + (i << 8);
            int r = idx >> 3, c4 = (idx & 7) << 2;
            cp16(sW + r * 32 + (c4 ^ (4 * (r & 7))),
                 W + (size_t)(bn + r) * C_DIM + c4);
        }
        CP_COMMIT();
    }

    for (int it = 0; it < 32; it++) {
        CP_WAIT0();
        __syncthreads();
        const float* cA = smg + (it & 1) * G_STAGE;
        const float* cW = cA + 8192;

        if (it < 31) {
            int k0 = (it + 1) << 5;
            float* sA = smg + ((it + 1) & 1) * G_STAGE;
            float* sW = sA + 8192;
#pragma unroll
            for (int i = 0; i < 8; i++) {
                int idx = tid + (i << 8);
                int r = idx >> 3, c4 = (idx & 7) << 2;
                cp16(sA + r * 32 + (c4 ^ (4 * (r & 7))),
                     A + (size_t)(bm + r) * C_DIM + k0 + c4);
            }
#pragma unroll
            for (int i = 0; i < 4; i++) {
                int idx = tid + (i << 8);
                int r = idx >> 3, c4 = (idx & 7) << 2;
                cp16(sW + r * 32 + (c4 ^ (4 * (r & 7))),
                     W + (size_t)(bn + r) * C_DIM + k0 + c4);
            }
            CP_COMMIT();
        }

#pragma unroll
        for (int kk = 0; kk < 32; kk += 8) {
            int c0 = (kk + u) ^ swz;
            int c1 = c0 ^ 4;
            unsigned af[4][4];
#pragma unroll
            for (int mf = 0; mf < 4; mf++) {
                int r0 = ((wm << 6) + (mf << 4) + qd) << 5;
                af[mf][0] = f2tf(cA[r0 + c0]);
                af[mf][1] = f2tf(cA[r0 + 256 + c0]);
                af[mf][2] = f2tf(cA[r0 + c1]);
                af[mf][3] = f2tf(cA[r0 + 256 + c1]);
            }
#pragma unroll
            for (int nf = 0; nf < 8; nf++) {
                int rn = ((wn << 6) + (nf << 3) + qd) << 5;
                unsigned b0 = f2tf(cW[rn + c0]);
                unsigned b1 = f2tf(cW[rn + c1]);
#pragma unroll
                for (int mf = 0; mf < 4; mf++)
                    mma_tf32(acc[mf][nf], af[mf][0], af[mf][1], af[mf][2], af[mf][3],
                             b0, b1);
            }
        }
    }

#pragma unroll
    for (int mf = 0; mf < 4; mf++) {
        int gr = bm + (wm << 6) + (mf << 4) + qd;
#pragma unroll
        for (int nf = 0; nf < 8; nf++) {
            int gc = bn + (wn << 6) + (nf << 3) + (u << 1);
            float2 bz = *(const float2*)(bias + gc);
            float2 o0 = make_float2(acc[mf][nf][0] + bz.x, acc[mf][nf][1] + bz.y);
            float2 o1 = make_float2(acc[mf][nf][2] + bz.x, acc[mf][nf][3] + bz.y);
            *(float2*)(out + (size_t)gr * C_DIM + gc)       = o0;
            *(float2*)(out + (size_t)(gr + 8) * C_DIM + gc) = o1;
        }
    }
}

// ---------------------------------------------------------------------------
// Flash attention, tf32 HMMA. CTA = 128 threads / 4 warps, 128 q rows
// (warp = 32 rows = 2 m-frags -> every K/V B-pair feeds 2 mmas).
// S chunk 64.  Q:[t][d], K:[s][d], V^T:[d][s], P:[t][s] (own region).
// All rows stride 64, swizzle col ^ 4*(row&7).
// ---------------------------------------------------------------------------
#define AQ 0
#define AK 8192
#define AV 12288
#define AP 16384
#define AM 24576
#define ATT_WORDS (AM + 64)

__global__ __launch_bounds__(128)
void attn_kernel(const float* __restrict__ qg,
                 const float* __restrict__ kg,
                 const float* __restrict__ vg,
                 const bool*  __restrict__ maskg,
                 float* __restrict__ outg) {
    extern __shared__ unsigned sm[];
    unsigned* Qs = sm + AQ;
    unsigned* Ks = sm + AK;
    unsigned* Vs = sm + AV;
    unsigned* Ps = sm + AP;
    float*   msk = (float*)(sm + AM);

    const int tid  = threadIdx.x;
    const int lane = tid & 31;
    const int w    = tid >> 5;     // 0..3
    const int u    = lane & 3;
    const int qd   = lane >> 2;
    const int swz  = 4 * qd;
    const int b    = blockIdx.z;
    const int h    = blockIdx.y;
    const int t0   = blockIdx.x << 7;
    const int R0   = w << 5;       // 32 rows / warp

    const float* qb = qg + ((size_t)b * T_DIM + t0) * C_DIM + h * D_DIM;
    const float* kb = kg + (size_t)b * S_DIM * C_DIM + h * D_DIM;
    const float* vb = vg + (size_t)b * S_DIM * C_DIM + h * D_DIM;
    const bool*  mb = maskg + (size_t)b * S_DIM;

    // Q tile: 128x64, scaled 1/8, tf32
#pragma unroll
    for (int i = 0; i < 16; i++) {
        int idx = tid + (i << 7);
        int r   = idx >> 4;
        int d0  = (idx & 15) << 2;
        float4 qv = *(const float4*)(qb + (size_t)r * C_DIM + d0);
        int o = (r << 6) + (d0 ^ (4 * (r & 7)));
        Qs[o + 0] = f2tf(qv.x * 0.125f); Qs[o + 1] = f2tf(qv.y * 0.125f);
        Qs[o + 2] = f2tf(qv.z * 0.125f); Qs[o + 3] = f2tf(qv.w * 0.125f);
    }

    float m_i[2][2], l_i[2][2], oacc[2][8][4];
#pragma unroll
    for (int mf = 0; mf < 2; mf++) {
        m_i[mf][0] = -1e30f; m_i[mf][1] = -1e30f;
        l_i[mf][0] = 0.f;    l_i[mf][1] = 0.f;
#pragma unroll
        for (int df = 0; df < 8; df++)
#pragma unroll
            for (int e = 0; e < 4; e++) oacc[mf][df][e] = 0.f;
    }

    for (int s0 = 0; s0 < S_DIM; s0 += 64) {
        __syncthreads();   // prev chunk's K/V consumers done
#pragma unroll
        for (int i = 0; i < 8; i++) {
            int idx = tid + (i << 7);
            int s   = idx >> 4;
            int d0  = (idx & 15) << 2;
            float4 kv = *(const float4*)(kb + (size_t)(s0 + s) * C_DIM + d0);
            int o = (s << 6) + (d0 ^ (4 * (s & 7)));
            Ks[o + 0] = f2tf(kv.x); Ks[o + 1] = f2tf(kv.y);
            Ks[o + 2] = f2tf(kv.z); Ks[o + 3] = f2tf(kv.w);
        }
#pragma unroll
        for (int i = 0; i < 8; i++) {
            int idx = tid + (i << 7);
            int s   = idx & 63;
            int d0  = (idx >> 6) << 2;
            float4 vv = *(const float4*)(vb + (size_t)(s0 + s) * C_DIM + d0);
            Vs[((d0 + 0) << 6) + (s ^ (4 * ((d0 + 0) & 7)))] = f2tf(vv.x);
            Vs[((d0 + 1) << 6) + (s ^ (4 * ((d0 + 1) & 7)))] = f2tf(vv.y);
            Vs[((d0 + 2) << 6) + (s ^ (4 * ((d0 + 2) & 7)))] = f2tf(vv.z);
            Vs[((d0 + 3) << 6) + (s ^ (4 * ((d0 + 3) & 7)))] = f2tf(vv.w);
        }
        if (tid < 64) msk[tid] = mb[s0 + tid] ? -1e30f : 0.f;
        __syncthreads();

        // ---- S = Q K^T ----
        float sc[2][8][4];
#pragma unroll
        for (int mf = 0; mf < 2; mf++)
#pragma unroll
            for (int nf = 0; nf < 8; nf++)
#pragma unroll
                for (int e = 0; e < 4; e++) sc[mf][nf][e] = 0.f;

#pragma unroll
        for (int kk = 0; kk < 8; kk++) {
            int c0 = ((kk << 3) + u) ^ swz;
            int c1 = c0 ^ 4;
            unsigned a[2][4];
#pragma unroll
            for (int mf = 0; mf < 2; mf++) {
                int ra = (R0 + (mf << 4) + qd) << 6;
                a[mf][0] = Qs[ra + c0];
                a[mf][1] = Qs[ra + 512 + c0];
                a[mf][2] = Qs[ra + c1];
                a[mf][3] = Qs[ra + 512 + c1];
            }
#pragma unroll
            for (int nf = 0; nf < 8; nf++) {
                int rb = ((nf << 3) + qd) << 6;
                unsigned b0 = Ks[rb + c0];
                unsigned b1 = Ks[rb + c1];
                mma_tf32(sc[0][nf], a[0][0], a[0][1], a[0][2], a[0][3], b0, b1);
                mma_tf32(sc[1][nf], a[1][0], a[1][1], a[1][2], a[1][3], b0, b1);
            }
        }

#pragma unroll
        for (int nf = 0; nf < 8; nf++) {
            float bm0 = msk[(nf << 3) + (u << 1)];
            float bm1 = msk[(nf << 3) + (u << 1) + 1];
#pragma unroll
            for (int mf = 0; mf < 2; mf++) {
                sc[mf][nf][0] += bm0; sc[mf][nf][1] += bm1;
                sc[mf][nf][2] += bm0; sc[mf][nf][3] += bm1;
            }
        }

        // ---- online softmax per m-frag ----
#pragma unroll
        for (int mf = 0; mf < 2; mf++) {
            float mx0 = -1e30f, mx1 = -1e30f;
#pragma unroll
            for (int nf = 0; nf < 8; nf++) {
                mx0 = fmaxf(mx0, fmaxf(sc[mf][nf][0], sc[mf][nf][1]));
                mx1 = fmaxf(mx1, fmaxf(sc[mf][nf][2], sc[mf][nf][3]));
            }
            mx0 = fmaxf(mx0, __shfl_xor_sync(0xffffffffu, mx0, 1));
            mx0 = fmaxf(mx0, __shfl_xor_sync(0xffffffffu, mx0, 2));
            mx1 = fmaxf(mx1, __shfl_xor_sync(0xffffffffu, mx1, 1));
            mx1 = fmaxf(mx1, __shfl_xor_sync(0xffffffffu, mx1, 2));
            float mn0 = fmaxf(m_i[mf][0], mx0), mn1 = fmaxf(m_i[mf][1], mx1);
            float cr0 = __expf(m_i[mf][0] - mn0), cr1 = __expf(m_i[mf][1] - mn1);
            m_i[mf][0] = mn0; m_i[mf][1] = mn1;
            float s0s = 0.f, s1s = 0.f;
#pragma unroll
            for (int nf = 0; nf < 8; nf++) {
                float p0 = __expf(sc[mf][nf][0] - mn0);
                float p1 = __expf(sc[mf][nf][1] - mn0);
                float p2 = __expf(sc[mf][nf][2] - mn1);
                float p3 = __expf(sc[mf][nf][3] - mn1);
                sc[mf][nf][0] = p0; sc[mf][nf][1] = p1;
                sc[mf][nf][2] = p2; sc[mf][nf][3] = p3;
                s0s += p0 + p1; s1s += p2 + p3;
            }
            s0s += __shfl_xor_sync(0xffffffffu, s0s, 1);
            s0s += __shfl_xor_sync(0xffffffffu, s0s, 2);
            s1s += __shfl_xor_sync(0xffffffffu, s1s, 1);
            s1s += __shfl_xor_sync(0xffffffffu, s1s, 2);
            l_i[mf][0] = l_i[mf][0] * cr0 + s0s;
            l_i[mf][1] = l_i[mf][1] * cr1 + s1s;
#pragma unroll
            for (int df = 0; df < 8; df++) {
                oacc[mf][df][0] *= cr0; oacc[mf][df][1] *= cr0;
                oacc[mf][df][2] *= cr1; oacc[mf][df][3] *= cr1;
            }
        }

        // ---- store P (warp-private region) ----
#pragma unroll
        for (int mf = 0; mf < 2; mf++) {
            int r0 = R0 + (mf << 4) + qd;
            int b0a = r0 << 6;
            int b1a = (r0 + 8) << 6;
#pragma unroll
            for (int nf = 0; nf < 8; nf++) {
                int pc = ((nf << 3) + (u << 1)) ^ swz;
                uint2 w0; w0.x = f2tf(sc[mf][nf][0]); w0.y = f2tf(sc[mf][nf][1]);
                uint2 w1; w1.x = f2tf(sc[mf][nf][2]); w1.y = f2tf(sc[mf][nf][3]);
                *(uint2*)&Ps[b0a + pc] = w0;
                *(uint2*)&Ps[b1a + pc] = w1;
            }
        }
        __syncwarp();

        // ---- O += P V ----
#pragma unroll
        for (int kk = 0; kk < 8; kk++) {
            int c0 = ((kk << 3) + u) ^ swz;
            int c1 = c0 ^ 4;
            unsigned a[2][4];
#pragma unroll
            for (int mf = 0; mf < 2; mf++) {
                int ra = (R0 + (mf << 4) + qd) << 6;
                a[mf][0] = Ps[ra + c0];
                a[mf][1] = Ps[ra + 512 + c0];
                a[mf][2] = Ps[ra + c1];
                a[mf][3] = Ps[ra + 512 + c1];
            }
#pragma unroll
            for (int df = 0; df < 8; df++) {
                int rb = ((df << 3) + qd) << 6;
                unsigned b0 = Vs[rb + c0];
                unsigned b1 = Vs[rb + c1];
                mma_tf32(oacc[0][df], a[0][0], a[0][1], a[0][2], a[0][3], b0, b1);
                mma_tf32(oacc[1][df], a[1][0], a[1][1], a[1][2], a[1][3], b0, b1);
            }
        }
    }

    // finalize
#pragma unroll
    for (int mf = 0; mf < 2; mf++) {
        float inv0 = 1.0f / l_i[mf][0];
        float inv1 = 1.0f / l_i[mf][1];
        int gr = t0 + R0 + (mf << 4) + qd;
#pragma unroll
        for (int df = 0; df < 8; df++) {
            int gc = h * D_DIM + (df << 3) + (u << 1);
            float2 o0 = make_float2(oacc[mf][df][0] * inv0, oacc[mf][df][1] * inv0);
            float2 o1 = make_float2(oacc[mf][df][2] * inv1, oacc[mf][df][3] * inv1);
            *(float2*)(outg + ((size_t)b * T_DIM + gr) * C_DIM + gc)     = o0;
            *(float2*)(outg + ((size_t)b * T_DIM + gr + 8) * C_DIM + gc) = o1;
        }
    }
}

extern "C" void kernel_launch(void* const* d_in, const int* in_sizes, int n_in,
                              void* d_out, int out_size) {
    const float* query = (const float*)d_in[0];
    const float* key   = (const float*)d_in[1];
    const float* value = (const float*)d_in[2];
    const bool*  kmask = (const bool*)d_in[3];
    const float* Wq = (const float*)d_in[4];
    const float* bq = (const float*)d_in[5];
    const float* Wk = (const float*)d_in[6];
    const float* bk = (const float*)d_in[7];
    const float* Wv = (const float*)d_in[8];
    const float* bv = (const float*)d_in[9];
    float* out = (float*)d_out;

    float *qp = nullptr, *kp = nullptr, *vp = nullptr;
    cudaGetSymbolAddress((void**)&qp, g_q);
    cudaGetSymbolAddress((void**)&kp, g_k);
    cudaGetSymbolAddress((void**)&vp, g_v);

    static int attr_set = 0;
    if (!attr_set) {
        cudaFuncSetAttribute(qkv_gemm, cudaFuncAttributeMaxDynamicSharedMemorySize,
                             2 * G_STAGE * sizeof(float));
        cudaFuncSetAttribute(attn_kernel, cudaFuncAttributeMaxDynamicSharedMemorySize,
                             ATT_WORDS * sizeof(unsigned));
        attr_set = 1;
    }

    dim3 gg(C_DIM / 128, (B_DIM * T_DIM) / 256, 3);   // (8, 32, 3)
    qkv_gemm<<<gg, 256, 2 * G_STAGE * sizeof(float)>>>(
        query, key, value, Wq, bq, Wk, bk, Wv, bv, qp, kp, vp);

    dim3 ga(T_DIM / 128, H_DIM, B_DIM);               // (16, 16, 4)
    attn_kernel<<<ga, 128, ATT_WORDS * sizeof(unsigned)>>>(qp, kp, vp, kmask, out);
}

// round 8
// speedup vs baseline: 2.9618x; 1.0528x over previous
#include <cuda_runtime.h>
#include <math.h>

#define B_DIM 4
#define T_DIM 2048
#define S_DIM 2048
#define C_DIM 1024
#define H_DIM 16
#define D_DIM 64

__device__ float g_q[(size_t)B_DIM * T_DIM * C_DIM];
__device__ float g_k[(size_t)B_DIM * S_DIM * C_DIM];
__device__ float g_v[(size_t)B_DIM * S_DIM * C_DIM];

__device__ __forceinline__ unsigned f2tf(float x) {
    unsigned u;
    asm("cvt.rna.tf32.f32 %0, %1;" : "=r"(u) : "f"(x));
    return u;
}

__device__ __forceinline__ void mma_tf32(float c[4],
                                         unsigned a0, unsigned a1, unsigned a2, unsigned a3,
                                         unsigned b0, unsigned b1) {
    asm volatile(
        "mma.sync.aligned.m16n8k8.row.col.f32.tf32.tf32.f32 "
        "{%0,%1,%2,%3}, {%4,%5,%6,%7}, {%8,%9}, {%0,%1,%2,%3};"
        : "+f"(c[0]), "+f"(c[1]), "+f"(c[2]), "+f"(c[3])
        : "r"(a0), "r"(a1), "r"(a2), "r"(a3), "r"(b0), "r"(b1));
}

__device__ __forceinline__ void cp16(void* s, const void* g) {
    unsigned sa = (unsigned)__cvta_generic_to_shared(s);
    asm volatile("cp.async.ca.shared.global [%0], [%1], 16;" :: "r"(sa), "l"(g));
}
#define CP_COMMIT() asm volatile("cp.async.commit_group;")
#define CP_WAIT0()  asm volatile("cp.async.wait_group 0;")
#define CP_WAIT1()  asm volatile("cp.async.wait_group 1;")

// ---------------------------------------------------------------------------
// QKV projection GEMM (z-batched, R4 version): out = A @ W^T + b
// Block 256x128, BK=32, 8 warps (4x2), warp tile 64x64, cp.async 2-stage.
// ---------------------------------------------------------------------------
#define G_STAGE 12288
__global__ __launch_bounds__(256)
void qkv_gemm(const float* __restrict__ Aq, const float* __restrict__ Ak,
              const float* __restrict__ Av,
              const float* __restrict__ Wq, const float* __restrict__ bq,
              const float* __restrict__ Wk, const float* __restrict__ bk,
              const float* __restrict__ Wv, const float* __restrict__ bv,
              float* __restrict__ oq, float* __restrict__ ok_,
              float* __restrict__ ov) {
    extern __shared__ float smg[];

    const float* A; const float* W; const float* bias; float* out;
    if (blockIdx.z == 0)      { A = Aq; W = Wq; bias = bq; out = oq; }
    else if (blockIdx.z == 1) { A = Ak; W = Wk; bias = bk; out = ok_; }
    else                      { A = Av; W = Wv; bias = bv; out = ov; }

    const int tid  = threadIdx.x;
    const int lane = tid & 31;
    const int w    = tid >> 5;
    const int wm   = w & 3;
    const int wn   = w >> 2;
    const int u    = lane & 3;
    const int qd   = lane >> 2;
    const int swz  = 4 * qd;
    const int bm   = blockIdx.y << 8;
    const int bn   = blockIdx.x << 7;

    float acc[4][8][4];
#pragma unroll
    for (int mf = 0; mf < 4; mf++)
#pragma unroll
        for (int nf = 0; nf < 8; nf++)
#pragma unroll
            for (int e = 0; e < 4; e++) acc[mf][nf][e] = 0.f;

    {
        float* sA = smg; float* sW = smg + 8192;
#pragma unroll
        for (int i = 0; i < 8; i++) {
            int idx = tid + (i << 8);
            int r = idx >> 3, c4 = (idx & 7) << 2;
            cp16(sA + r * 32 + (c4 ^ (4 * (r & 7))),
                 A + (size_t)(bm + r) * C_DIM + c4);
        }
#pragma unroll
        for (int i = 0; i < 4; i++) {
            int idx = tid + (i << 8);
            int r = idx >> 3, c4 = (idx & 7) << 2;
            cp16(sW + r * 32 + (c4 ^ (4 * (r & 7))),
                 W + (size_t)(bn + r) * C_DIM + c4);
        }
        CP_COMMIT();
    }

    for (int it = 0; it < 32; it++) {
        CP_WAIT0();
        __syncthreads();
        const float* cA = smg + (it & 1) * G_STAGE;
        const float* cW = cA + 8192;

        if (it < 31) {
            int k0 = (it + 1) << 5;
            float* sA = smg + ((it + 1) & 1) * G_STAGE;
            float* sW = sA + 8192;
#pragma unroll
            for (int i = 0; i < 8; i++) {
                int idx = tid + (i << 8);
                int r = idx >> 3, c4 = (idx & 7) << 2;
                cp16(sA + r * 32 + (c4 ^ (4 * (r & 7))),
                     A + (size_t)(bm + r) * C_DIM + k0 + c4);
            }
#pragma unroll
            for (int i = 0; i < 4; i++) {
                int idx = tid + (i << 8);
                int r = idx >> 3, c4 = (idx & 7) << 2;
                cp16(sW + r * 32 + (c4 ^ (4 * (r & 7))),
                     W + (size_t)(bn + r) * C_DIM + k0 + c4);
            }
            CP_COMMIT();
        }

#pragma unroll
        for (int kk = 0; kk < 32; kk += 8) {
            int c0 = (kk + u) ^ swz;
            int c1 = c0 ^ 4;
            unsigned af[4][4];
#pragma unroll
            for (int mf = 0; mf < 4; mf++) {
                int r0 = ((wm << 6) + (mf << 4) + qd) << 5;
                af[mf][0] = f2tf(cA[r0 + c0]);
                af[mf][1] = f2tf(cA[r0 + 256 + c0]);
                af[mf][2] = f2tf(cA[r0 + c1]);
                af[mf][3] = f2tf(cA[r0 + 256 + c1]);
            }
#pragma unroll
            for (int nf = 0; nf < 8; nf++) {
                int rn = ((wn << 6) + (nf << 3) + qd) << 5;
                unsigned b0 = f2tf(cW[rn + c0]);
                unsigned b1 = f2tf(cW[rn + c1]);
#pragma unroll
                for (int mf = 0; mf < 4; mf++)
                    mma_tf32(acc[mf][nf], af[mf][0], af[mf][1], af[mf][2], af[mf][3],
                             b0, b1);
            }
        }
    }

#pragma unroll
    for (int mf = 0; mf < 4; mf++) {
        int gr = bm + (wm << 6) + (mf << 4) + qd;
#pragma unroll
        for (int nf = 0; nf < 8; nf++) {
            int gc = bn + (wn << 6) + (nf << 3) + (u << 1);
            float2 bz = *(const float2*)(bias + gc);
            float2 o0 = make_float2(acc[mf][nf][0] + bz.x, acc[mf][nf][1] + bz.y);
            float2 o1 = make_float2(acc[mf][nf][2] + bz.x, acc[mf][nf][3] + bz.y);
            *(float2*)(out + (size_t)gr * C_DIM + gc)       = o0;
            *(float2*)(out + (size_t)(gr + 8) * C_DIM + gc) = o1;
        }
    }
}

// ---------------------------------------------------------------------------
// Flash attention, tf32 HMMA. 4 warps x 32 q-rows (mf=2, nf=8).
// P overlays the K buffer in 32-col halves (K dead after QK^T) -> smem 64.3KB
// -> 3 CTAs/SM.  __launch_bounds__(128,3) caps regs at 170.
// Ph layout: [r][c ^ 4*(r&7)], stride 32 words.
// ---------------------------------------------------------------------------
#define AQ  0
#define AKP 8192
#define AV  12288
#define AM  16384
#define ATT_WORDS (AM + 64)

__global__ __launch_bounds__(128, 3)
void attn_kernel(const float* __restrict__ qg,
                 const float* __restrict__ kg,
                 const float* __restrict__ vg,
                 const bool*  __restrict__ maskg,
                 float* __restrict__ outg) {
    extern __shared__ unsigned sm[];
    unsigned* Qs  = sm + AQ;
    unsigned* KPs = sm + AKP;    // K: [s][d^4(s&7)] stride 64; later Ph: [r][c^4(r&7)] stride 32
    unsigned* Vs  = sm + AV;
    float*   msk  = (float*)(sm + AM);

    const int tid  = threadIdx.x;
    const int lane = tid & 31;
    const int w    = tid >> 5;
    const int u    = lane & 3;
    const int qd   = lane >> 2;
    const int swz  = 4 * qd;
    const int b    = blockIdx.z;
    const int h    = blockIdx.y;
    const int t0   = blockIdx.x << 7;
    const int R0   = w << 5;

    const float* qb = qg + ((size_t)b * T_DIM + t0) * C_DIM + h * D_DIM;
    const float* kb = kg + (size_t)b * S_DIM * C_DIM + h * D_DIM;
    const float* vb = vg + (size_t)b * S_DIM * C_DIM + h * D_DIM;
    const bool*  mb = maskg + (size_t)b * S_DIM;

#pragma unroll
    for (int i = 0; i < 16; i++) {
        int idx = tid + (i << 7);
        int r   = idx >> 4;
        int d0  = (idx & 15) << 2;
        float4 qv = *(const float4*)(qb + (size_t)r * C_DIM + d0);
        int o = (r << 6) + (d0 ^ (4 * (r & 7)));
        Qs[o + 0] = f2tf(qv.x * 0.125f); Qs[o + 1] = f2tf(qv.y * 0.125f);
        Qs[o + 2] = f2tf(qv.z * 0.125f); Qs[o + 3] = f2tf(qv.w * 0.125f);
    }

    float m_i[2][2], l_i[2][2], oacc[2][8][4];
#pragma unroll
    for (int mf = 0; mf < 2; mf++) {
        m_i[mf][0] = -1e30f; m_i[mf][1] = -1e30f;
        l_i[mf][0] = 0.f;    l_i[mf][1] = 0.f;
#pragma unroll
        for (int df = 0; df < 8; df++)
#pragma unroll
            for (int e = 0; e < 4; e++) oacc[mf][df][e] = 0.f;
    }

    for (int s0 = 0; s0 < S_DIM; s0 += 64) {
        __syncthreads();   // prior PV half-2 readers done (V + Ph dead)
        // K chunk: [s][d ^ 4*(s&7)], stride 64
#pragma unroll
        for (int i = 0; i < 8; i++) {
            int idx = tid + (i << 7);
            int s   = idx >> 4;
            int d0  = (idx & 15) << 2;
            float4 kv = *(const float4*)(kb + (size_t)(s0 + s) * C_DIM + d0);
            int o = (s << 6) + (d0 ^ (4 * (s & 7)));
            KPs[o + 0] = f2tf(kv.x); KPs[o + 1] = f2tf(kv.y);
            KPs[o + 2] = f2tf(kv.z); KPs[o + 3] = f2tf(kv.w);
        }
        // V chunk transposed: [d][s ^ 4*(d&7)], stride 64
#pragma unroll
        for (int i = 0; i < 8; i++) {
            int idx = tid + (i << 7);
            int s   = idx & 63;
            int d0  = (idx >> 6) << 2;
            float4 vv = *(const float4*)(vb + (size_t)(s0 + s) * C_DIM + d0);
            Vs[((d0 + 0) << 6) + (s ^ (4 * ((d0 + 0) & 7)))] = f2tf(vv.x);
            Vs[((d0 + 1) << 6) + (s ^ (4 * ((d0 + 1) & 7)))] = f2tf(vv.y);
            Vs[((d0 + 2) << 6) + (s ^ (4 * ((d0 + 2) & 7)))] = f2tf(vv.z);
            Vs[((d0 + 3) << 6) + (s ^ (4 * ((d0 + 3) & 7)))] = f2tf(vv.w);
        }
        if (tid < 64) msk[tid] = mb[s0 + tid] ? -1e30f : 0.f;
        __syncthreads();

        // ---- S = Q K^T ----
        float sc[2][8][4];
#pragma unroll
        for (int mf = 0; mf < 2; mf++)
#pragma unroll
            for (int nf = 0; nf < 8; nf++)
#pragma unroll
                for (int e = 0; e < 4; e++) sc[mf][nf][e] = 0.f;

#pragma unroll
        for (int kk = 0; kk < 8; kk++) {
            int c0 = ((kk << 3) + u) ^ swz;
            int c1 = c0 ^ 4;
            unsigned a[2][4];
#pragma unroll
            for (int mf = 0; mf < 2; mf++) {
                int ra = (R0 + (mf << 4) + qd) << 6;
                a[mf][0] = Qs[ra + c0];
                a[mf][1] = Qs[ra + 512 + c0];
                a[mf][2] = Qs[ra + c1];
                a[mf][3] = Qs[ra + 512 + c1];
            }
#pragma unroll
            for (int nf = 0; nf < 8; nf++) {
                int rb = ((nf << 3) + qd) << 6;
                unsigned b0 = KPs[rb + c0];
                unsigned b1 = KPs[rb + c1];
                mma_tf32(sc[0][nf], a[0][0], a[0][1], a[0][2], a[0][3], b0, b1);
                mma_tf32(sc[1][nf], a[1][0], a[1][1], a[1][2], a[1][3], b0, b1);
            }
        }

        // mask bias
#pragma unroll
        for (int nf = 0; nf < 8; nf++) {
            float bm0 = msk[(nf << 3) + (u << 1)];
            float bm1 = msk[(nf << 3) + (u << 1) + 1];
#pragma unroll
            for (int mf = 0; mf < 2; mf++) {
                sc[mf][nf][0] += bm0; sc[mf][nf][1] += bm1;
                sc[mf][nf][2] += bm0; sc[mf][nf][3] += bm1;
            }
        }

        // ---- online softmax (full 64-col rows) ----
#pragma unroll
        for (int mf = 0; mf < 2; mf++) {
            float mx0 = -1e30f, mx1 = -1e30f;
#pragma unroll
            for (int nf = 0; nf < 8; nf++) {
                mx0 = fmaxf(mx0, fmaxf(sc[mf][nf][0], sc[mf][nf][1]));
                mx1 = fmaxf(mx1, fmaxf(sc[mf][nf][2], sc[mf][nf][3]));
            }
            mx0 = fmaxf(mx0, __shfl_xor_sync(0xffffffffu, mx0, 1));
            mx0 = fmaxf(mx0, __shfl_xor_sync(0xffffffffu, mx0, 2));
            mx1 = fmaxf(mx1, __shfl_xor_sync(0xffffffffu, mx1, 1));
            mx1 = fmaxf(mx1, __shfl_xor_sync(0xffffffffu, mx1, 2));
            float mn0 = fmaxf(m_i[mf][0], mx0), mn1 = fmaxf(m_i[mf][1], mx1);
            float cr0 = __expf(m_i[mf][0] - mn0), cr1 = __expf(m_i[mf][1] - mn1);
            m_i[mf][0] = mn0; m_i[mf][1] = mn1;
            float s0s = 0.f, s1s = 0.f;
#pragma unroll
            for (int nf = 0; nf < 8; nf++) {
                float p0 = __expf(sc[mf][nf][0] - mn0);
                float p1 = __expf(sc[mf][nf][1] - mn0);
                float p2 = __expf(sc[mf][nf][2] - mn1);
                float p3 = __expf(sc[mf][nf][3] - mn1);
                sc[mf][nf][0] = p0; sc[mf][nf][1] = p1;
                sc[mf][nf][2] = p2; sc[mf][nf][3] = p3;
                s0s += p0 + p1; s1s += p2 + p3;
            }
            s0s += __shfl_xor_sync(0xffffffffu, s0s, 1);
            s0s += __shfl_xor_sync(0xffffffffu, s0s, 2);
            s1s += __shfl_xor_sync(0xffffffffu, s1s, 1);
            s1s += __shfl_xor_sync(0xffffffffu, s1s, 2);
            l_i[mf][0] = l_i[mf][0] * cr0 + s0s;
            l_i[mf][1] = l_i[mf][1] * cr1 + s1s;
#pragma unroll
            for (int df = 0; df < 8; df++) {
                oacc[mf][df][0] *= cr0; oacc[mf][df][1] *= cr0;
                oacc[mf][df][2] *= cr1; oacc[mf][df][3] *= cr1;
            }
        }

        // ---- PV in two 32-col halves; P overlays the K buffer ----
#pragma unroll
        for (int half = 0; half < 2; half++) {
            __syncthreads();   // K reads (h=0) / prior Ph reads (h=1) complete
            // write P half: rows R0..R0+31, local cols 0..31
#pragma unroll
            for (int mf = 0; mf < 2; mf++) {
                int r0 = R0 + (mf << 4) + qd;
#pragma unroll
                for (int nfl = 0; nfl < 4; nfl++) {
                    int nf = (half << 2) + nfl;
                    int cl = (nfl << 3) + (u << 1);
                    uint2 w0; w0.x = f2tf(sc[mf][nf][0]); w0.y = f2tf(sc[mf][nf][1]);
                    uint2 w1; w1.x = f2tf(sc[mf][nf][2]); w1.y = f2tf(sc[mf][nf][3]);
                    *(uint2*)&KPs[(r0 << 5) + (cl ^ (4 * (r0 & 7)))]       = w0;
                    *(uint2*)&KPs[((r0 + 8) << 5) + (cl ^ (4 * ((r0 + 8) & 7)))] = w1;
                }
            }
            __syncthreads();   // Ph visible to all warps (same-warp only, but cheap+safe)

            // O += Phalf @ Vhalf  (kk local 0..3, global s = half*32 + ...)
#pragma unroll
            for (int kkl = 0; kkl < 4; kkl++) {
                int cv0 = ((half << 5) + (kkl << 3) + u) ^ swz;
                int cv1 = cv0 ^ 4;
                int cpl0 = ((kkl << 3) + u) ^ swz;
                int cpl1 = cpl0 ^ 4;
                unsigned a[2][4];
#pragma unroll
                for (int mf = 0; mf < 2; mf++) {
                    int ra = (R0 + (mf << 4) + qd) << 5;
                    a[mf][0] = KPs[ra + cpl0];
                    a[mf][1] = KPs[ra + 256 + cpl0];   // +8 rows * 32
                    a[mf][2] = KPs[ra + cpl1];
                    a[mf][3] = KPs[ra + 256 + cpl1];
                }
#pragma unroll
                for (int df = 0; df < 8; df++) {
                    int rb = ((df << 3) + qd) << 6;
                    unsigned b0 = Vs[rb + cv0];
                    unsigned b1 = Vs[rb + cv1];
                    mma_tf32(oacc[0][df], a[0][0], a[0][1], a[0][2], a[0][3], b0, b1);
                    mma_tf32(oacc[1][df], a[1][0], a[1][1], a[1][2], a[1][3], b0, b1);
                }
            }
        }
    }

    // finalize
#pragma unroll
    for (int mf = 0; mf < 2; mf++) {
        float inv0 = 1.0f / l_i[mf][0];
        float inv1 = 1.0f / l_i[mf][1];
        int gr = t0 + R0 + (mf << 4) + qd;
#pragma unroll
        for (int df = 0; df < 8; df++) {
            int gc = h * D_DIM + (df << 3) + (u << 1);
            float2 o0 = make_float2(oacc[mf][df][0] * inv0, oacc[mf][df][1] * inv0);
            float2 o1 = make_float2(oacc[mf][df][2] * inv1, oacc[mf][df][3] * inv1);
            *(float2*)(outg + ((size_t)b * T_DIM + gr) * C_DIM + gc)     = o0;
            *(float2*)(outg + ((size_t)b * T_DIM + gr + 8) * C_DIM + gc) = o1;
        }
    }
}

extern "C" void kernel_launch(void* const* d_in, const int* in_sizes, int n_in,
                              void* d_out, int out_size) {
    const float* query = (const float*)d_in[0];
    const float* key   = (const float*)d_in[1];
    const float* value = (const float*)d_in[2];
    const bool*  kmask = (const bool*)d_in[3];
    const float* Wq = (const float*)d_in[4];
    const float* bq = (const float*)d_in[5];
    const float* Wk = (const float*)d_in[6];
    const float* bk = (const float*)d_in[7];
    const float* Wv = (const float*)d_in[8];
    const float* bv = (const float*)d_in[9];
    float* out = (float*)d_out;

    float *qp = nullptr, *kp = nullptr, *vp = nullptr;
    cudaGetSymbolAddress((void**)&qp, g_q);
    cudaGetSymbolAddress((void**)&kp, g_k);
    cudaGetSymbolAddress((void**)&vp, g_v);

    static int attr_set = 0;
    if (!attr_set) {
        cudaFuncSetAttribute(qkv_gemm, cudaFuncAttributeMaxDynamicSharedMemorySize,
                             2 * G_STAGE * sizeof(float));
        cudaFuncSetAttribute(attn_kernel, cudaFuncAttributeMaxDynamicSharedMemorySize,
                             ATT_WORDS * sizeof(unsigned));
        attr_set = 1;
    }

    dim3 gg(C_DIM / 128, (B_DIM * T_DIM) / 256, 3);   // (8, 32, 3)
    qkv_gemm<<<gg, 256, 2 * G_STAGE * sizeof(float)>>>(
        query, key, value, Wq, bq, Wk, bk, Wv, bv, qp, kp, vp);

    dim3 ga(T_DIM / 128, H_DIM, B_DIM);               // (16, 16, 4)
    attn_kernel<<<ga, 128, ATT_WORDS * sizeof(unsigned)>>>(qp, kp, vp, kmask, out);
}

// round 9
// speedup vs baseline: 2.9793x; 1.0059x over previous
#include <cuda_runtime.h>
#include <math.h>

#define B_DIM 4
#define T_DIM 2048
#define S_DIM 2048
#define C_DIM 1024
#define H_DIM 16
#define D_DIM 64

__device__ float g_q[(size_t)B_DIM * T_DIM * C_DIM];
__device__ float g_k[(size_t)B_DIM * S_DIM * C_DIM];
__device__ float g_v[(size_t)B_DIM * S_DIM * C_DIM];

__device__ __forceinline__ unsigned f2tf(float x) {
    unsigned u;
    asm("cvt.rna.tf32.f32 %0, %1;" : "=r"(u) : "f"(x));
    return u;
}

__device__ __forceinline__ void mma_tf32(float c[4],
                                         unsigned a0, unsigned a1, unsigned a2, unsigned a3,
                                         unsigned b0, unsigned b1) {
    asm volatile(
        "mma.sync.aligned.m16n8k8.row.col.f32.tf32.tf32.f32 "
        "{%0,%1,%2,%3}, {%4,%5,%6,%7}, {%8,%9}, {%0,%1,%2,%3};"
        : "+f"(c[0]), "+f"(c[1]), "+f"(c[2]), "+f"(c[3])
        : "r"(a0), "r"(a1), "r"(a2), "r"(a3), "r"(b0), "r"(b1));
}

__device__ __forceinline__ void cp16(void* s, const void* g) {
    unsigned sa = (unsigned)__cvta_generic_to_shared(s);
    asm volatile("cp.async.ca.shared.global [%0], [%1], 16;" :: "r"(sa), "l"(g));
}
#define CP_COMMIT() asm volatile("cp.async.commit_group;")
#define CP_WAIT0()  asm volatile("cp.async.wait_group 0;")
#define CP_WAIT1()  asm volatile("cp.async.wait_group 1;")

// ---------------------------------------------------------------------------
// QKV projection GEMM (z-batched, R4 version): out = A @ W^T + b
// Block 256x128, BK=32, 8 warps (4x2), warp tile 64x64, cp.async 2-stage.
// ---------------------------------------------------------------------------
#define G_STAGE 12288
__global__ __launch_bounds__(256)
void qkv_gemm(const float* __restrict__ Aq, const float* __restrict__ Ak,
              const float* __restrict__ Av,
              const float* __restrict__ Wq, const float* __restrict__ bq,
              const float* __restrict__ Wk, const float* __restrict__ bk,
              const float* __restrict__ Wv, const float* __restrict__ bv,
              float* __restrict__ oq, float* __restrict__ ok_,
              float* __restrict__ ov) {
    extern __shared__ float smg[];

    const float* A; const float* W; const float* bias; float* out;
    if (blockIdx.z == 0)      { A = Aq; W = Wq; bias = bq; out = oq; }
    else if (blockIdx.z == 1) { A = Ak; W = Wk; bias = bk; out = ok_; }
    else                      { A = Av; W = Wv; bias = bv; out = ov; }

    const int tid  = threadIdx.x;
    const int lane = tid & 31;
    const int w    = tid >> 5;
    const int wm   = w & 3;
    const int wn   = w >> 2;
    const int u    = lane & 3;
    const int qd   = lane >> 2;
    const int swz  = 4 * qd;
    const int bm   = blockIdx.y << 8;
    const int bn   = blockIdx.x << 7;

    float acc[4][8][4];
#pragma unroll
    for (int mf = 0; mf < 4; mf++)
#pragma unroll
        for (int nf = 0; nf < 8; nf++)
#pragma unroll
            for (int e = 0; e < 4; e++) acc[mf][nf][e] = 0.f;

    {
        float* sA = smg; float* sW = smg + 8192;
#pragma unroll
        for (int i = 0; i < 8; i++) {
            int idx = tid + (i << 8);
            int r = idx >> 3, c4 = (idx & 7) << 2;
            cp16(sA + r * 32 + (c4 ^ (4 * (r & 7))),
                 A + (size_t)(bm + r) * C_DIM + c4);
        }
#pragma unroll
        for (int i = 0; i < 4; i++) {
            int idx = tid + (i << 8);
            int r = idx >> 3, c4 = (idx & 7) << 2;
            cp16(sW + r * 32 + (c4 ^ (4 * (r & 7))),
                 W + (size_t)(bn + r) * C_DIM + c4);
        }
        CP_COMMIT();
    }

    for (int it = 0; it < 32; it++) {
        CP_WAIT0();
        __syncthreads();
        const float* cA = smg + (it & 1) * G_STAGE;
        const float* cW = cA + 8192;

        if (it < 31) {
            int k0 = (it + 1) << 5;
            float* sA = smg + ((it + 1) & 1) * G_STAGE;
            float* sW = sA + 8192;
#pragma unroll
            for (int i = 0; i < 8; i++) {
                int idx = tid + (i << 8);
                int r = idx >> 3, c4 = (idx & 7) << 2;
                cp16(sA + r * 32 + (c4 ^ (4 * (r & 7))),
                     A + (size_t)(bm + r) * C_DIM + k0 + c4);
            }
#pragma unroll
            for (int i = 0; i < 4; i++) {
                int idx = tid + (i << 8);
                int r = idx >> 3, c4 = (idx & 7) << 2;
                cp16(sW + r * 32 + (c4 ^ (4 * (r & 7))),
                     W + (size_t)(bn + r) * C_DIM + k0 + c4);
            }
            CP_COMMIT();
        }

#pragma unroll
        for (int kk = 0; kk < 32; kk += 8) {
            int c0 = (kk + u) ^ swz;
            int c1 = c0 ^ 4;
            unsigned af[4][4];
#pragma unroll
            for (int mf = 0; mf < 4; mf++) {
                int r0 = ((wm << 6) + (mf << 4) + qd) << 5;
                af[mf][0] = f2tf(cA[r0 + c0]);
                af[mf][1] = f2tf(cA[r0 + 256 + c0]);
                af[mf][2] = f2tf(cA[r0 + c1]);
                af[mf][3] = f2tf(cA[r0 + 256 + c1]);
            }
#pragma unroll
            for (int nf = 0; nf < 8; nf++) {
                int rn = ((wn << 6) + (nf << 3) + qd) << 5;
                unsigned b0 = f2tf(cW[rn + c0]);
                unsigned b1 = f2tf(cW[rn + c1]);
#pragma unroll
                for (int mf = 0; mf < 4; mf++)
                    mma_tf32(acc[mf][nf], af[mf][0], af[mf][1], af[mf][2], af[mf][3],
                             b0, b1);
            }
        }
    }

#pragma unroll
    for (int mf = 0; mf < 4; mf++) {
        int gr = bm + (wm << 6) + (mf << 4) + qd;
#pragma unroll
        for (int nf = 0; nf < 8; nf++) {
            int gc = bn + (wn << 6) + (nf << 3) + (u << 1);
            float2 bz = *(const float2*)(bias + gc);
            float2 o0 = make_float2(acc[mf][nf][0] + bz.x, acc[mf][nf][1] + bz.y);
            float2 o1 = make_float2(acc[mf][nf][2] + bz.x, acc[mf][nf][3] + bz.y);
            *(float2*)(out + (size_t)gr * C_DIM + gc)       = o0;
            *(float2*)(out + (size_t)(gr + 8) * C_DIM + gc) = o1;
        }
    }
}

// ---------------------------------------------------------------------------
// Flash attention, tf32 HMMA. 4 warps x 32 q-rows (mf=2, nf=8).
// P overlays the K buffer in 32-col halves (K dead after QK^T) -> smem 64.3KB
// -> 3 CTAs/SM.  __launch_bounds__(128,3) caps regs at 170.
// Ph layout: [r][c ^ 4*(r&7)], stride 32 words.
// ---------------------------------------------------------------------------
#define AQ  0
#define AKP 8192
#define AV  12288
#define AM  16384
#define ATT_WORDS (AM + 64)

__global__ __launch_bounds__(128, 3)
void attn_kernel(const float* __restrict__ qg,
                 const float* __restrict__ kg,
                 const float* __restrict__ vg,
                 const bool*  __restrict__ maskg,
                 float* __restrict__ outg) {
    extern __shared__ unsigned sm[];
    unsigned* Qs  = sm + AQ;
    unsigned* KPs = sm + AKP;    // K: [s][d^4(s&7)] stride 64; later Ph: [r][c^4(r&7)] stride 32
    unsigned* Vs  = sm + AV;
    float*   msk  = (float*)(sm + AM);

    const int tid  = threadIdx.x;
    const int lane = tid & 31;
    const int w    = tid >> 5;
    const int u    = lane & 3;
    const int qd   = lane >> 2;
    const int swz  = 4 * qd;
    const int b    = blockIdx.z;
    const int h    = blockIdx.y;
    const int t0   = blockIdx.x << 7;
    const int R0   = w << 5;

    const float* qb = qg + ((size_t)b * T_DIM + t0) * C_DIM + h * D_DIM;
    const float* kb = kg + (size_t)b * S_DIM * C_DIM + h * D_DIM;
    const float* vb = vg + (size_t)b * S_DIM * C_DIM + h * D_DIM;
    const bool*  mb = maskg + (size_t)b * S_DIM;

#pragma unroll
    for (int i = 0; i < 16; i++) {
        int idx = tid + (i << 7);
        int r   = idx >> 4;
        int d0  = (idx & 15) << 2;
        float4 qv = *(const float4*)(qb + (size_t)r * C_DIM + d0);
        int o = (r << 6) + (d0 ^ (4 * (r & 7)));
        Qs[o + 0] = f2tf(qv.x * 0.125f); Qs[o + 1] = f2tf(qv.y * 0.125f);
        Qs[o + 2] = f2tf(qv.z * 0.125f); Qs[o + 3] = f2tf(qv.w * 0.125f);
    }

    float m_i[2][2], l_i[2][2], oacc[2][8][4];
#pragma unroll
    for (int mf = 0; mf < 2; mf++) {
        m_i[mf][0] = -1e30f; m_i[mf][1] = -1e30f;
        l_i[mf][0] = 0.f;    l_i[mf][1] = 0.f;
#pragma unroll
        for (int df = 0; df < 8; df++)
#pragma unroll
            for (int e = 0; e < 4; e++) oacc[mf][df][e] = 0.f;
    }

    for (int s0 = 0; s0 < S_DIM; s0 += 64) {
        __syncthreads();   // prior PV half-2 readers done (V + Ph dead)
        // K chunk: [s][d ^ 4*(s&7)], stride 64
#pragma unroll
        for (int i = 0; i < 8; i++) {
            int idx = tid + (i << 7);
            int s   = idx >> 4;
            int d0  = (idx & 15) << 2;
            float4 kv = *(const float4*)(kb + (size_t)(s0 + s) * C_DIM + d0);
            int o = (s << 6) + (d0 ^ (4 * (s & 7)));
            KPs[o + 0] = f2tf(kv.x); KPs[o + 1] = f2tf(kv.y);
            KPs[o + 2] = f2tf(kv.z); KPs[o + 3] = f2tf(kv.w);
        }
        // V chunk transposed: [d][s ^ 4*(d&7)], stride 64
#pragma unroll
        for (int i = 0; i < 8; i++) {
            int idx = tid + (i << 7);
            int s   = idx & 63;
            int d0  = (idx >> 6) << 2;
            float4 vv = *(const float4*)(vb + (size_t)(s0 + s) * C_DIM + d0);
            Vs[((d0 + 0) << 6) + (s ^ (4 * ((d0 + 0) & 7)))] = f2tf(vv.x);
            Vs[((d0 + 1) << 6) + (s ^ (4 * ((d0 + 1) & 7)))] = f2tf(vv.y);
            Vs[((d0 + 2) << 6) + (s ^ (4 * ((d0 + 2) & 7)))] = f2tf(vv.z);
            Vs[((d0 + 3) << 6) + (s ^ (4 * ((d0 + 3) & 7)))] = f2tf(vv.w);
        }
        if (tid < 64) msk[tid] = mb[s0 + tid] ? -1e30f : 0.f;
        __syncthreads();

        // ---- S = Q K^T ----
        float sc[2][8][4];
#pragma unroll
        for (int mf = 0; mf < 2; mf++)
#pragma unroll
            for (int nf = 0; nf < 8; nf++)
#pragma unroll
                for (int e = 0; e < 4; e++) sc[mf][nf][e] = 0.f;

#pragma unroll
        for (int kk = 0; kk < 8; kk++) {
            int c0 = ((kk << 3) + u) ^ swz;
            int c1 = c0 ^ 4;
            unsigned a[2][4];
#pragma unroll
            for (int mf = 0; mf < 2; mf++) {
                int ra = (R0 + (mf << 4) + qd) << 6;
                a[mf][0] = Qs[ra + c0];
                a[mf][1] = Qs[ra + 512 + c0];
                a[mf][2] = Qs[ra + c1];
                a[mf][3] = Qs[ra + 512 + c1];
            }
#pragma unroll
            for (int nf = 0; nf < 8; nf++) {
                int rb = ((nf << 3) + qd) << 6;
                unsigned b0 = KPs[rb + c0];
                unsigned b1 = KPs[rb + c1];
                mma_tf32(sc[0][nf], a[0][0], a[0][1], a[0][2], a[0][3], b0, b1);
                mma_tf32(sc[1][nf], a[1][0], a[1][1], a[1][2], a[1][3], b0, b1);
            }
        }

        // mask bias
#pragma unroll
        for (int nf = 0; nf < 8; nf++) {
            float bm0 = msk[(nf << 3) + (u << 1)];
            float bm1 = msk[(nf << 3) + (u << 1) + 1];
#pragma unroll
            for (int mf = 0; mf < 2; mf++) {
                sc[mf][nf][0] += bm0; sc[mf][nf][1] += bm1;
                sc[mf][nf][2] += bm0; sc[mf][nf][3] += bm1;
            }
        }

        // ---- online softmax (full 64-col rows) ----
#pragma unroll
        for (int mf = 0; mf < 2; mf++) {
            float mx0 = -1e30f, mx1 = -1e30f;
#pragma unroll
            for (int nf = 0; nf < 8; nf++) {
                mx0 = fmaxf(mx0, fmaxf(sc[mf][nf][0], sc[mf][nf][1]));
                mx1 = fmaxf(mx1, fmaxf(sc[mf][nf][2], sc[mf][nf][3]));
            }
            mx0 = fmaxf(mx0, __shfl_xor_sync(0xffffffffu, mx0, 1));
            mx0 = fmaxf(mx0, __shfl_xor_sync(0xffffffffu, mx0, 2));
            mx1 = fmaxf(mx1, __shfl_xor_sync(0xffffffffu, mx1, 1));
            mx1 = fmaxf(mx1, __shfl_xor_sync(0xffffffffu, mx1, 2));
            float mn0 = fmaxf(m_i[mf][0], mx0), mn1 = fmaxf(m_i[mf][1], mx1);
            float cr0 = __expf(m_i[mf][0] - mn0), cr1 = __expf(m_i[mf][1] - mn1);
            m_i[mf][0] = mn0; m_i[mf][1] = mn1;
            float s0s = 0.f, s1s = 0.f;
#pragma unroll
            for (int nf = 0; nf < 8; nf++) {
                float p0 = __expf(sc[mf][nf][0] - mn0);
                float p1 = __expf(sc[mf][nf][1] - mn0);
                float p2 = __expf(sc[mf][nf][2] - mn1);
                float p3 = __expf(sc[mf][nf][3] - mn1);
                sc[mf][nf][0] = p0; sc[mf][nf][1] = p1;
                sc[mf][nf][2] = p2; sc[mf][nf][3] = p3;
                s0s += p0 + p1; s1s += p2 + p3;
            }
            s0s += __shfl_xor_sync(0xffffffffu, s0s, 1);
            s0s += __shfl_xor_sync(0xffffffffu, s0s, 2);
            s1s += __shfl_xor_sync(0xffffffffu, s1s, 1);
            s1s += __shfl_xor_sync(0xffffffffu, s1s, 2);
            l_i[mf][0] = l_i[mf][0] * cr0 + s0s;
            l_i[mf][1] = l_i[mf][1] * cr1 + s1s;
#pragma unroll
            for (int df = 0; df < 8; df++) {
                oacc[mf][df][0] *= cr0; oacc[mf][df][1] *= cr0;
                oacc[mf][df][2] *= cr1; oacc[mf][df][3] *= cr1;
            }
        }

        // ---- PV in two 32-col halves; P overlays the K buffer ----
#pragma unroll
        for (int half = 0; half < 2; half++) {
            __syncthreads();   // K reads (h=0) / prior Ph reads (h=1) complete
            // write P half: rows R0..R0+31, local cols 0..31
#pragma unroll
            for (int mf = 0; mf < 2; mf++) {
                int r0 = R0 + (mf << 4) + qd;
#pragma unroll
                for (int nfl = 0; nfl < 4; nfl++) {
                    int nf = (half << 2) + nfl;
                    int cl = (nfl << 3) + (u << 1);
                    uint2 w0; w0.x = f2tf(sc[mf][nf][0]); w0.y = f2tf(sc[mf][nf][1]);
                    uint2 w1; w1.x = f2tf(sc[mf][nf][2]); w1.y = f2tf(sc[mf][nf][3]);
                    *(uint2*)&KPs[(r0 << 5) + (cl ^ (4 * (r0 & 7)))]       = w0;
                    *(uint2*)&KPs[((r0 + 8) << 5) + (cl ^ (4 * ((r0 + 8) & 7)))] = w1;
                }
            }
            __syncthreads();   // Ph visible to all warps (same-warp only, but cheap+safe)

            // O += Phalf @ Vhalf  (kk local 0..3, global s = half*32 + ...)
#pragma unroll
            for (int kkl = 0; kkl < 4; kkl++) {
                int cv0 = ((half << 5) + (kkl << 3) + u) ^ swz;
                int cv1 = cv0 ^ 4;
                int cpl0 = ((kkl << 3) + u) ^ swz;
                int cpl1 = cpl0 ^ 4;
                unsigned a[2][4];
#pragma unroll
                for (int mf = 0; mf < 2; mf++) {
                    int ra = (R0 + (mf << 4) + qd) << 5;
                    a[mf][0] = KPs[ra + cpl0];
                    a[mf][1] = KPs[ra + 256 + cpl0];   // +8 rows * 32
                    a[mf][2] = KPs[ra + cpl1];
                    a[mf][3] = KPs[ra + 256 + cpl1];
                }
#pragma unroll
                for (int df = 0; df < 8; df++) {
                    int rb = ((df << 3) + qd) << 6;
                    unsigned b0 = Vs[rb + cv0];
                    unsigned b1 = Vs[rb + cv1];
                    mma_tf32(oacc[0][df], a[0][0], a[0][1], a[0][2], a[0][3], b0, b1);
                    mma_tf32(oacc[1][df], a[1][0], a[1][1], a[1][2], a[1][3], b0, b1);
                }
            }
        }
    }

    // finalize
#pragma unroll
    for (int mf = 0; mf < 2; mf++) {
        float inv0 = 1.0f / l_i[mf][0];
        float inv1 = 1.0f / l_i[mf][1];
        int gr = t0 + R0 + (mf << 4) + qd;
#pragma unroll
        for (int df = 0; df < 8; df++) {
            int gc = h * D_DIM + (df << 3) + (u << 1);
            float2 o0 = make_float2(oacc[mf][df][0] * inv0, oacc[mf][df][1] * inv0);
            float2 o1 = make_float2(oacc[mf][df][2] * inv1, oacc[mf][df][3] * inv1);
            *(float2*)(outg + ((size_t)b * T_DIM + gr) * C_DIM + gc)     = o0;
            *(float2*)(outg + ((size_t)b * T_DIM + gr + 8) * C_DIM + gc) = o1;
        }
    }
}

extern "C" void kernel_launch(void* const* d_in, const int* in_sizes, int n_in,
                              void* d_out, int out_size) {
    const float* query = (const float*)d_in[0];
    const float* key   = (const float*)d_in[1];
    const float* value = (const float*)d_in[2];
    const bool*  kmask = (const bool*)d_in[3];
    const float* Wq = (const float*)d_in[4];
    const float* bq = (const float*)d_in[5];
    const float* Wk = (const float*)d_in[6];
    const float* bk = (const float*)d_in[7];
    const float* Wv = (const float*)d_in[8];
    const float* bv = (const float*)d_in[9];
    float* out = (float*)d_out;

    float *qp = nullptr, *kp = nullptr, *vp = nullptr;
    cudaGetSymbolAddress((void**)&qp, g_q);
    cudaGetSymbolAddress((void**)&kp, g_k);
    cudaGetSymbolAddress((void**)&vp, g_v);

    static int attr_set = 0;
    if (!attr_set) {
        cudaFuncSetAttribute(qkv_gemm, cudaFuncAttributeMaxDynamicSharedMemorySize,
                             2 * G_STAGE * sizeof(float));
        cudaFuncSetAttribute(attn_kernel, cudaFuncAttributeMaxDynamicSharedMemorySize,
                             ATT_WORDS * sizeof(unsigned));
        attr_set = 1;
    }

    dim3 gg(C_DIM / 128, (B_DIM * T_DIM) / 256, 3);   // (8, 32, 3)
    qkv_gemm<<<gg, 256, 2 * G_STAGE * sizeof(float)>>>(
        query, key, value, Wq, bq, Wk, bk, Wv, bv, qp, kp, vp);

    dim3 ga(T_DIM / 128, H_DIM, B_DIM);               // (16, 16, 4)
    attn_kernel<<<ga, 128, ATT_WORDS * sizeof(unsigned)>>>(qp, kp, vp, kmask, out);
}

// round 12
// speedup vs baseline: 5.9797x; 2.0070x over previous
#include <cuda_runtime.h>
#include <cuda_fp16.h>
#include <math.h>
#include <stdint.h>

#define B_DIM 4
#define T_DIM 2048
#define S_DIM 2048
#define C_DIM 1024
#define H_DIM 16
#define D_DIM 64
#define ACT_N ((size_t)B_DIM * T_DIM * C_DIM)

__device__ __half g_q[ACT_N];
__device__ __half g_k[ACT_N];
__device__ __half g_v[ACT_N];
__device__ __half g_xq[ACT_N];
__device__ __half g_xk[ACT_N];
__device__ __half g_xv[ACT_N];
__device__ __half g_wq[(size_t)C_DIM * C_DIM];
__device__ __half g_wk[(size_t)C_DIM * C_DIM];
__device__ __half g_wv[(size_t)C_DIM * C_DIM];

__device__ __forceinline__ void mma_f16(float c[4],
                                        unsigned a0, unsigned a1, unsigned a2, unsigned a3,
                                        unsigned b0, unsigned b1) {
    asm volatile(
        "mma.sync.aligned.m16n8k16.row.col.f32.f16.f16.f32 "
        "{%0,%1,%2,%3}, {%4,%5,%6,%7}, {%8,%9}, {%0,%1,%2,%3};"
        : "+f"(c[0]), "+f"(c[1]), "+f"(c[2]), "+f"(c[3])
        : "r"(a0), "r"(a1), "r"(a2), "r"(a3), "r"(b0), "r"(b1));
}

__device__ __forceinline__ void cp16(void* s, const void* g) {
    unsigned sa = (unsigned)__cvta_generic_to_shared(s);
    asm volatile("cp.async.ca.shared.global [%0], [%1], 16;" :: "r"(sa), "l"(g));
}
#define CP_COMMIT() asm volatile("cp.async.commit_group;")
#define CP_WAIT0()  asm volatile("cp.async.wait_group 0;")

__device__ __forceinline__ void ldsm4(unsigned r[4], const void* p) {
    unsigned a = (unsigned)__cvta_generic_to_shared(p);
    asm volatile("ldmatrix.sync.aligned.m8n8.x4.shared.b16 {%0,%1,%2,%3}, [%4];"
                 : "=r"(r[0]), "=r"(r[1]), "=r"(r[2]), "=r"(r[3]) : "r"(a));
}
__device__ __forceinline__ void ldsm4t(unsigned r[4], const void* p) {
    unsigned a = (unsigned)__cvta_generic_to_shared(p);
    asm volatile("ldmatrix.sync.aligned.m8n8.x4.trans.shared.b16 {%0,%1,%2,%3}, [%4];"
                 : "=r"(r[0]), "=r"(r[1]), "=r"(r[2]), "=r"(r[3]) : "r"(a));
}

__device__ __forceinline__ unsigned packh2(float x, float y) {
    __half2 h = __floats2half2_rn(x, y);
    return *(unsigned*)&h;
}

// ---------------------------------------------------------------------------
// fp32 -> fp16 conversion (grid-stride)
// ---------------------------------------------------------------------------
__global__ void cvt_h_kernel(const float* __restrict__ in,
                             __half* __restrict__ out, int n4) {
    int i = blockIdx.x * blockDim.x + threadIdx.x;
    int stride = gridDim.x * blockDim.x;
    for (; i < n4; i += stride) {
        float4 v = ((const float4*)in)[i];
        uint2 o;
        o.x = packh2(v.x, v.y);
        o.y = packh2(v.z, v.w);
        ((uint2*)out)[i] = o;
    }
}

// ---------------------------------------------------------------------------
// fp16 QKV GEMM (z-batched): out = (A @ W^T + b) * scale  (fp16 out)
// Block 256x128, BK=32, 8 warps (4x2), warp 64x64, ldmatrix + m16n8k16,
// cp.async 2-stage. smem rows: 16 words (32 halves).
// Swizzle: colw ^ (((r>>1)&3)<<2)  -- stays inside the 16-word row,
// conflict-free for 8-row ldmatrix segments (even rows {c^0..c^3},
// odd rows the 4+ complement).
// ---------------------------------------------------------------------------
#define GH_STAGE 6144
__device__ __forceinline__ int gsw(int r) {
    return ((r >> 1) & 3) << 2;
}

__global__ __launch_bounds__(256)
void qkv_gemm_h(const __half* __restrict__ Aq, const __half* __restrict__ Ak,
                const __half* __restrict__ Av,
                const __half* __restrict__ Wq, const float* __restrict__ bq,
                const __half* __restrict__ Wk, const float* __restrict__ bk,
                const __half* __restrict__ Wv, const float* __restrict__ bv,
                __half* __restrict__ oq, __half* __restrict__ ok_,
                __half* __restrict__ ov) {
    extern __shared__ unsigned smg[];

    const __half* A; const __half* W; const float* bias; __half* out;
    float qscale;
    if (blockIdx.z == 0)      { A = Aq; W = Wq; bias = bq; out = oq;  qscale = 0.125f; }
    else if (blockIdx.z == 1) { A = Ak; W = Wk; bias = bk; out = ok_; qscale = 1.0f; }
    else                      { A = Av; W = Wv; bias = bv; out = ov;  qscale = 1.0f; }

    const int tid  = threadIdx.x;
    const int lane = tid & 31;
    const int w    = tid >> 5;
    const int wm   = w & 3;
    const int wn   = w >> 2;
    const int u    = lane & 3;
    const int qd   = lane >> 2;
    const int l    = lane & 7;
    const int grp  = lane >> 3;
    const int bm   = blockIdx.y << 8;
    const int bn   = blockIdx.x << 7;

    float acc[4][8][4];
#pragma unroll
    for (int mf = 0; mf < 4; mf++)
#pragma unroll
        for (int nf = 0; nf < 8; nf++)
#pragma unroll
            for (int e = 0; e < 4; e++) acc[mf][nf][e] = 0.f;

    auto load_tile = [&](int k0, int stage) {
        unsigned* sA = smg + stage * GH_STAGE;
        unsigned* sB = sA + 4096;
#pragma unroll
        for (int i = 0; i < 4; i++) {
            int idx = tid + (i << 8);
            int r = idx >> 2, g = idx & 3;
            cp16(sA + r * 16 + ((g << 2) ^ gsw(r)),
                 A + (size_t)(bm + r) * C_DIM + k0 + g * 8);
        }
#pragma unroll
        for (int i = 0; i < 2; i++) {
            int idx = tid + (i << 8);
            int r = idx >> 2, g = idx & 3;
            cp16(sB + r * 16 + ((g << 2) ^ gsw(r)),
                 W + (size_t)(bn + r) * C_DIM + k0 + g * 8);
        }
        CP_COMMIT();
    };

    load_tile(0, 0);

    for (int it = 0; it < 32; it++) {
        CP_WAIT0();
        __syncthreads();
        const unsigned* cA = smg + (it & 1) * GH_STAGE;
        const unsigned* cB = cA + 4096;
        if (it < 31) load_tile((it + 1) << 5, (it + 1) & 1);

#pragma unroll
        for (int kb = 0; kb < 2; kb++) {
            unsigned af[4][4];
#pragma unroll
            for (int mf = 0; mf < 4; mf++) {
                int row = (wm << 6) + (mf << 4) + ((grp & 1) << 3) + l;
                int colw = (kb << 3) + ((grp >> 1) << 2);
                ldsm4(af[mf], cA + row * 16 + (colw ^ gsw(row)));
            }
            unsigned bf[8][2];
#pragma unroll
            for (int j = 0; j < 4; j++) {
                int row = (wn << 6) + (j << 4) + ((grp >> 1) << 3) + l;
                int colw = (kb << 3) + ((grp & 1) << 2);
                unsigned r4[4];
                ldsm4(r4, cB + row * 16 + (colw ^ gsw(row)));
                bf[2 * j][0] = r4[0];     bf[2 * j][1] = r4[1];
                bf[2 * j + 1][0] = r4[2]; bf[2 * j + 1][1] = r4[3];
            }
#pragma unroll
            for (int nf = 0; nf < 8; nf++)
#pragma unroll
                for (int mf = 0; mf < 4; mf++)
                    mma_f16(acc[mf][nf], af[mf][0], af[mf][1], af[mf][2], af[mf][3],
                            bf[nf][0], bf[nf][1]);
        }
    }

#pragma unroll
    for (int mf = 0; mf < 4; mf++) {
        int gr = bm + (wm << 6) + (mf << 4) + qd;
#pragma unroll
        for (int nf = 0; nf < 8; nf++) {
            int gc = bn + (wn << 6) + (nf << 3) + (u << 1);
            float2 bz = *(const float2*)(bias + gc);
            unsigned o0 = packh2((acc[mf][nf][0] + bz.x) * qscale,
                                 (acc[mf][nf][1] + bz.y) * qscale);
            unsigned o1 = packh2((acc[mf][nf][2] + bz.x) * qscale,
                                 (acc[mf][nf][3] + bz.y) * qscale);
            *(unsigned*)(out + (size_t)gr * C_DIM + gc)       = o0;
            *(unsigned*)(out + (size_t)(gr + 8) * C_DIM + gc) = o1;
        }
    }
}

// ---------------------------------------------------------------------------
// fp16 flash attention. 4 warps x 32 q-rows, chunk 64, P in registers.
// smem rows 32 words (64 halves), swizzle colw ^ ((r&7)<<2). K/V double-
// buffered cp.async; one __syncthreads per chunk.
// ---------------------------------------------------------------------------
#define AT_Q   0
#define AT_K   4096
#define AT_V   8192
#define AT_M   12288
#define AT_WORDS 12416

__global__ __launch_bounds__(128, 3)
void attn_h(const __half* __restrict__ qg,
            const __half* __restrict__ kg,
            const __half* __restrict__ vg,
            const bool*  __restrict__ maskg,
            float* __restrict__ outg) {
    extern __shared__ unsigned sm[];
    unsigned* Qs = sm + AT_Q;
    unsigned* Kd[2] = { sm + AT_K, sm + AT_K + 2048 };
    unsigned* Vd[2] = { sm + AT_V, sm + AT_V + 2048 };
    float*    msk[2] = { (float*)(sm + AT_M), (float*)(sm + AT_M) + 64 };

    const int tid  = threadIdx.x;
    const int lane = tid & 31;
    const int w    = tid >> 5;
    const int u    = lane & 3;
    const int qd   = lane >> 2;
    const int l    = lane & 7;
    const int grp  = lane >> 3;
    const int b    = blockIdx.z;
    const int h    = blockIdx.y;
    const int t0   = blockIdx.x << 7;
    const int R0   = w << 5;

    const __half* qb = qg + ((size_t)b * T_DIM + t0) * C_DIM + h * D_DIM;
    const __half* kb = kg + (size_t)b * S_DIM * C_DIM + h * D_DIM;
    const __half* vb = vg + (size_t)b * S_DIM * C_DIM + h * D_DIM;
    const bool*  mb = maskg + (size_t)b * S_DIM;

    auto load_kv = [&](int chunk, int buf) {
        const __half* ks = kb + ((size_t)chunk << 6) * C_DIM;
        const __half* vs = vb + ((size_t)chunk << 6) * C_DIM;
#pragma unroll
        for (int i = 0; i < 4; i++) {
            int idx = tid + (i << 7);
            int r = idx >> 3, seg = idx & 7;
            int word = r * 32 + ((seg << 2) ^ ((r & 7) << 2));
            cp16(Kd[buf] + word, ks + (size_t)r * C_DIM + (seg << 3));
            cp16(Vd[buf] + word, vs + (size_t)r * C_DIM + (seg << 3));
        }
        CP_COMMIT();
    };

    // prologue: Q + chunk0 in one group; mask for chunk0
    {
#pragma unroll
        for (int i = 0; i < 8; i++) {
            int idx = tid + (i << 7);
            int r = idx >> 3, seg = idx & 7;
            int word = r * 32 + ((seg << 2) ^ ((r & 7) << 2));
            cp16(Qs + word, qb + (size_t)r * C_DIM + (seg << 3));
        }
#pragma unroll
        for (int i = 0; i < 4; i++) {
            int idx = tid + (i << 7);
            int r = idx >> 3, seg = idx & 7;
            int word = r * 32 + ((seg << 2) ^ ((r & 7) << 2));
            cp16(Kd[0] + word, kb + (size_t)r * C_DIM + (seg << 3));
            cp16(Vd[0] + word, vb + (size_t)r * C_DIM + (seg << 3));
        }
        CP_COMMIT();
        if (tid < 64) msk[0][tid] = mb[tid] ? -1e30f : 0.f;
    }

    float m_i[2][2], l_i[2][2], oacc[2][8][4];
#pragma unroll
    for (int mf = 0; mf < 2; mf++) {
        m_i[mf][0] = -1e30f; m_i[mf][1] = -1e30f;
        l_i[mf][0] = 0.f;    l_i[mf][1] = 0.f;
#pragma unroll
        for (int df = 0; df < 8; df++)
#pragma unroll
            for (int e = 0; e < 4; e++) oacc[mf][df][e] = 0.f;
    }

    const int NCH = S_DIM / 64;
#pragma unroll 1
    for (int i = 0; i < NCH; i++) {
        CP_WAIT0();
        __syncthreads();
        const int buf = i & 1;
        const unsigned* K = Kd[buf];
        const unsigned* V = Vd[buf];
        const float* mk = msk[buf];

        if (i + 1 < NCH) {
            load_kv(i + 1, buf ^ 1);
            if (tid < 64) msk[buf ^ 1][tid] = mb[((i + 1) << 6) + tid] ? -1e30f : 0.f;
        }

        // ---- S = Q K^T ----
        float sc[2][8][4];
#pragma unroll
        for (int mf = 0; mf < 2; mf++)
#pragma unroll
            for (int nf = 0; nf < 8; nf++)
#pragma unroll
                for (int e = 0; e < 4; e++) sc[mf][nf][e] = 0.f;

#pragma unroll
        for (int kbk = 0; kbk < 4; kbk++) {
            unsigned bkf[8][2];
#pragma unroll
            for (int j = 0; j < 4; j++) {
                int row = (j << 4) + ((grp >> 1) << 3) + l;
                int colw = (kbk << 3) + ((grp & 1) << 2);
                unsigned r4[4];
                ldsm4(r4, K + row * 32 + (colw ^ ((row & 7) << 2)));
                bkf[2 * j][0] = r4[0];     bkf[2 * j][1] = r4[1];
                bkf[2 * j + 1][0] = r4[2]; bkf[2 * j + 1][1] = r4[3];
            }
#pragma unroll
            for (int mf = 0; mf < 2; mf++) {
                int row = R0 + (mf << 4) + ((grp & 1) << 3) + l;
                int colw = (kbk << 3) + ((grp >> 1) << 2);
                unsigned a4[4];
                ldsm4(a4, Qs + row * 32 + (colw ^ ((row & 7) << 2)));
#pragma unroll
                for (int nf = 0; nf < 8; nf++)
                    mma_f16(sc[mf][nf], a4[0], a4[1], a4[2], a4[3],
                            bkf[nf][0], bkf[nf][1]);
            }
        }

        // mask bias
#pragma unroll
        for (int nf = 0; nf < 8; nf++) {
            float bm0 = mk[(nf << 3) + (u << 1)];
            float bm1 = mk[(nf << 3) + (u << 1) + 1];
#pragma unroll
            for (int mf = 0; mf < 2; mf++) {
                sc[mf][nf][0] += bm0; sc[mf][nf][1] += bm1;
                sc[mf][nf][2] += bm0; sc[mf][nf][3] += bm1;
            }
        }

        // ---- online softmax ----
#pragma unroll
        for (int mf = 0; mf < 2; mf++) {
            float mx0 = -1e30f, mx1 = -1e30f;
#pragma unroll
            for (int nf = 0; nf < 8; nf++) {
                mx0 = fmaxf(mx0, fmaxf(sc[mf][nf][0], sc[mf][nf][1]));
                mx1 = fmaxf(mx1, fmaxf(sc[mf][nf][2], sc[mf][nf][3]));
            }
            mx0 = fmaxf(mx0, __shfl_xor_sync(0xffffffffu, mx0, 1));
            mx0 = fmaxf(mx0, __shfl_xor_sync(0xffffffffu, mx0, 2));
            mx1 = fmaxf(mx1, __shfl_xor_sync(0xffffffffu, mx1, 1));
            mx1 = fmaxf(mx1, __shfl_xor_sync(0xffffffffu, mx1, 2));
            float mn0 = fmaxf(m_i[mf][0], mx0), mn1 = fmaxf(m_i[mf][1], mx1);
            float cr0 = __expf(m_i[mf][0] - mn0), cr1 = __expf(m_i[mf][1] - mn1);
            m_i[mf][0] = mn0; m_i[mf][1] = mn1;
            float s0s = 0.f, s1s = 0.f;
#pragma unroll
            for (int nf = 0; nf < 8; nf++) {
                float p0 = __expf(sc[mf][nf][0] - mn0);
                float p1 = __expf(sc[mf][nf][1] - mn0);
                float p2 = __expf(sc[mf][nf][2] - mn1);
                float p3 = __expf(sc[mf][nf][3] - mn1);
                sc[mf][nf][0] = p0; sc[mf][nf][1] = p1;
                sc[mf][nf][2] = p2; sc[mf][nf][3] = p3;
                s0s += p0 + p1; s1s += p2 + p3;
            }
            s0s += __shfl_xor_sync(0xffffffffu, s0s, 1);
            s0s += __shfl_xor_sync(0xffffffffu, s0s, 2);
            s1s += __shfl_xor_sync(0xffffffffu, s1s, 1);
            s1s += __shfl_xor_sync(0xffffffffu, s1s, 2);
            l_i[mf][0] = l_i[mf][0] * cr0 + s0s;
            l_i[mf][1] = l_i[mf][1] * cr1 + s1s;
#pragma unroll
            for (int df = 0; df < 8; df++) {
                oacc[mf][df][0] *= cr0; oacc[mf][df][1] *= cr0;
                oacc[mf][df][2] *= cr1; oacc[mf][df][3] *= cr1;
            }
        }

        // ---- O += P V  (P from registers; V via ldmatrix.trans) ----
#pragma unroll
        for (int ks = 0; ks < 4; ks++) {
            unsigned bv[8][2];
#pragma unroll
            for (int dfp = 0; dfp < 4; dfp++) {
                int row = (ks << 4) + ((grp & 1) << 3) + l;
                int colw = (dfp << 3) + ((grp >> 1) << 2);
                unsigned r4[4];
                ldsm4t(r4, V + row * 32 + (colw ^ ((row & 7) << 2)));
                bv[2 * dfp][0] = r4[0];     bv[2 * dfp][1] = r4[1];
                bv[2 * dfp + 1][0] = r4[2]; bv[2 * dfp + 1][1] = r4[3];
            }
#pragma unroll
            for (int mf = 0; mf < 2; mf++) {
                unsigned a0 = packh2(sc[mf][2 * ks][0], sc[mf][2 * ks][1]);
                unsigned a1 = packh2(sc[mf][2 * ks][2], sc[mf][2 * ks][3]);
                unsigned a2 = packh2(sc[mf][2 * ks + 1][0], sc[mf][2 * ks + 1][1]);
                unsigned a3 = packh2(sc[mf][2 * ks + 1][2], sc[mf][2 * ks + 1][3]);
#pragma unroll
                for (int df = 0; df < 8; df++)
                    mma_f16(oacc[mf][df], a0, a1, a2, a3, bv[df][0], bv[df][1]);
            }
        }
    }

    // finalize
#pragma unroll
    for (int mf = 0; mf < 2; mf++) {
        float inv0 = 1.0f / l_i[mf][0];
        float inv1 = 1.0f / l_i[mf][1];
        int gr = t0 + R0 + (mf << 4) + qd;
#pragma unroll
        for (int df = 0; df < 8; df++) {
            int gc = h * D_DIM + (df << 3) + (u << 1);
            float2 o0 = make_float2(oacc[mf][df][0] * inv0, oacc[mf][df][1] * inv0);
            float2 o1 = make_float2(oacc[mf][df][2] * inv1, oacc[mf][df][3] * inv1);
            *(float2*)(outg + ((size_t)b * T_DIM + gr) * C_DIM + gc)     = o0;
            *(float2*)(outg + ((size_t)b * T_DIM + gr + 8) * C_DIM + gc) = o1;
        }
    }
}

extern "C" void kernel_launch(void* const* d_in, const int* in_sizes, int n_in,
                              void* d_out, int out_size) {
    const float* query = (const float*)d_in[0];
    const float* key   = (const float*)d_in[1];
    const float* value = (const float*)d_in[2];
    const bool*  kmask = (const bool*)d_in[3];
    const float* Wq = (const float*)d_in[4];
    const float* bq = (const float*)d_in[5];
    const float* Wk = (const float*)d_in[6];
    const float* bk = (const float*)d_in[7];
    const float* Wv = (const float*)d_in[8];
    const float* bv = (const float*)d_in[9];
    float* out = (float*)d_out;

    __half *qp, *kp, *vp, *xq, *xk, *xv, *wq, *wk, *wv;
    cudaGetSymbolAddress((void**)&qp, g_q);
    cudaGetSymbolAddress((void**)&kp, g_k);
    cudaGetSymbolAddress((void**)&vp, g_v);
    cudaGetSymbolAddress((void**)&xq, g_xq);
    cudaGetSymbolAddress((void**)&xk, g_xk);
    cudaGetSymbolAddress((void**)&xv, g_xv);
    cudaGetSymbolAddress((void**)&wq, g_wq);
    cudaGetSymbolAddress((void**)&wk, g_wk);
    cudaGetSymbolAddress((void**)&wv, g_wv);

    static int attr_set = 0;
    if (!attr_set) {
        cudaFuncSetAttribute(qkv_gemm_h, cudaFuncAttributeMaxDynamicSharedMemorySize,
                             2 * GH_STAGE * sizeof(unsigned));
        cudaFuncSetAttribute(attn_h, cudaFuncAttributeMaxDynamicSharedMemorySize,
                             AT_WORDS * sizeof(unsigned));
        attr_set = 1;
    }

    const int nAct = (int)(ACT_N / 4);
    const int nW   = C_DIM * C_DIM / 4;
    cvt_h_kernel<<<2048, 256>>>(query, xq, nAct);
    cvt_h_kernel<<<2048, 256>>>(key,   xk, nAct);
    cvt_h_kernel<<<2048, 256>>>(value, xv, nAct);
    cvt_h_kernel<<<512, 256>>>(Wq, wq, nW);
    cvt_h_kernel<<<512, 256>>>(Wk, wk, nW);
    cvt_h_kernel<<<512, 256>>>(Wv, wv, nW);

    dim3 gg(C_DIM / 128, (B_DIM * T_DIM) / 256, 3);   // (8, 32, 3)
    qkv_gemm_h<<<gg, 256, 2 * GH_STAGE * sizeof(unsigned)>>>(
        xq, xk, xv, wq, bq, wk, bk, wv, bv, qp, kp, vp);

    dim3 ga(T_DIM / 128, H_DIM, B_DIM);               // (16, 16, 4)
    attn_h<<<ga, 128, AT_WORDS * sizeof(unsigned)>>>(qp, kp, vp, kmask, out);
}

// round 13
// speedup vs baseline: 6.4272x; 1.0748x over previous
#include <cuda_runtime.h>
#include <cuda_fp16.h>
#include <math.h>
#include <stdint.h>

#define B_DIM 4
#define T_DIM 2048
#define S_DIM 2048
#define C_DIM 1024
#define H_DIM 16
#define D_DIM 64
#define ACT_N ((size_t)B_DIM * T_DIM * C_DIM)

__device__ __half g_q[ACT_N];
__device__ __half g_k[ACT_N];
__device__ __half g_v[ACT_N];
__device__ __half g_xq[ACT_N];
__device__ __half g_xk[ACT_N];
__device__ __half g_xv[ACT_N];
__device__ __half g_wq[(size_t)C_DIM * C_DIM];
__device__ __half g_wk[(size_t)C_DIM * C_DIM];
__device__ __half g_wv[(size_t)C_DIM * C_DIM];

__device__ __forceinline__ void mma_f16(float c[4],
                                        unsigned a0, unsigned a1, unsigned a2, unsigned a3,
                                        unsigned b0, unsigned b1) {
    asm volatile(
        "mma.sync.aligned.m16n8k16.row.col.f32.f16.f16.f32 "
        "{%0,%1,%2,%3}, {%4,%5,%6,%7}, {%8,%9}, {%0,%1,%2,%3};"
        : "+f"(c[0]), "+f"(c[1]), "+f"(c[2]), "+f"(c[3])
        : "r"(a0), "r"(a1), "r"(a2), "r"(a3), "r"(b0), "r"(b1));
}

// L2-only (cg) streaming cp.async: these tiles are read-once per SM.
__device__ __forceinline__ void cp16(void* s, const void* g) {
    unsigned sa = (unsigned)__cvta_generic_to_shared(s);
    asm volatile("cp.async.cg.shared.global [%0], [%1], 16;" :: "r"(sa), "l"(g));
}
#define CP_COMMIT() asm volatile("cp.async.commit_group;")
#define CP_WAIT0()  asm volatile("cp.async.wait_group 0;")

__device__ __forceinline__ void ldsm4(unsigned r[4], const void* p) {
    unsigned a = (unsigned)__cvta_generic_to_shared(p);
    asm volatile("ldmatrix.sync.aligned.m8n8.x4.shared.b16 {%0,%1,%2,%3}, [%4];"
                 : "=r"(r[0]), "=r"(r[1]), "=r"(r[2]), "=r"(r[3]) : "r"(a));
}
__device__ __forceinline__ void ldsm4t(unsigned r[4], const void* p) {
    unsigned a = (unsigned)__cvta_generic_to_shared(p);
    asm volatile("ldmatrix.sync.aligned.m8n8.x4.trans.shared.b16 {%0,%1,%2,%3}, [%4];"
                 : "=r"(r[0]), "=r"(r[1]), "=r"(r[2]), "=r"(r[3]) : "r"(a));
}

__device__ __forceinline__ unsigned packh2(float x, float y) {
    __half2 h = __floats2half2_rn(x, y);
    return *(unsigned*)&h;
}

// ---------------------------------------------------------------------------
// Fused fp32 -> fp16 conversion for all 6 arrays in ONE launch.
// ---------------------------------------------------------------------------
struct CvtJobs {
    const float4* s[6];
    uint2*        d[6];
    int           n4[6];
};

__global__ void cvt_all_kernel(CvtJobs j) {
    const int stride = gridDim.x * blockDim.x;
    const int base = blockIdx.x * blockDim.x + threadIdx.x;
#pragma unroll 1
    for (int seg = 0; seg < 6; seg++) {
        const float4* __restrict__ src = j.s[seg];
        uint2* __restrict__ dst = j.d[seg];
        const int n = j.n4[seg];
        for (int i = base; i < n; i += stride) {
            float4 v = __ldcs(src + i);
            uint2 o;
            o.x = packh2(v.x, v.y);
            o.y = packh2(v.z, v.w);
            __stcs(dst + i, o);
        }
    }
}

// ---------------------------------------------------------------------------
// fp16 QKV GEMM (z-batched): out = (A @ W^T + b) * scale  (fp16 out)
// Block 256x128, BK=32, 8 warps (4x2), warp 64x64, ldmatrix + m16n8k16,
// cp.async 2-stage. smem rows: 16 words (32 halves), swizzle gsw(r).
// Q projection output is scaled by 0.125 * log2(e)  (base-2 softmax).
// ---------------------------------------------------------------------------
#define GH_STAGE 6144
#define QSCALE_LOG2E 0.18033688011112042f   // 0.125 * log2(e)
__device__ __forceinline__ int gsw(int r) {
    return ((r >> 1) & 3) << 2;
}

__global__ __launch_bounds__(256)
void qkv_gemm_h(const __half* __restrict__ Aq, const __half* __restrict__ Ak,
                const __half* __restrict__ Av,
                const __half* __restrict__ Wq, const float* __restrict__ bq,
                const __half* __restrict__ Wk, const float* __restrict__ bk,
                const __half* __restrict__ Wv, const float* __restrict__ bv,
                __half* __restrict__ oq, __half* __restrict__ ok_,
                __half* __restrict__ ov) {
    extern __shared__ unsigned smg[];

    const __half* A; const __half* W; const float* bias; __half* out;
    float qscale;
    if (blockIdx.z == 0)      { A = Aq; W = Wq; bias = bq; out = oq;  qscale = QSCALE_LOG2E; }
    else if (blockIdx.z == 1) { A = Ak; W = Wk; bias = bk; out = ok_; qscale = 1.0f; }
    else                      { A = Av; W = Wv; bias = bv; out = ov;  qscale = 1.0f; }

    const int tid  = threadIdx.x;
    const int lane = tid & 31;
    const int w    = tid >> 5;
    const int wm   = w & 3;
    const int wn   = w >> 2;
    const int u    = lane & 3;
    const int qd   = lane >> 2;
    const int l    = lane & 7;
    const int grp  = lane >> 3;
    const int bm   = blockIdx.y << 8;
    const int bn   = blockIdx.x << 7;

    float acc[4][8][4];
#pragma unroll
    for (int mf = 0; mf < 4; mf++)
#pragma unroll
        for (int nf = 0; nf < 8; nf++)
#pragma unroll
            for (int e = 0; e < 4; e++) acc[mf][nf][e] = 0.f;

    auto load_tile = [&](int k0, int stage) {
        unsigned* sA = smg + stage * GH_STAGE;
        unsigned* sB = sA + 4096;
#pragma unroll
        for (int i = 0; i < 4; i++) {
            int idx = tid + (i << 8);
            int r = idx >> 2, g = idx & 3;
            cp16(sA + r * 16 + ((g << 2) ^ gsw(r)),
                 A + (size_t)(bm + r) * C_DIM + k0 + g * 8);
        }
#pragma unroll
        for (int i = 0; i < 2; i++) {
            int idx = tid + (i << 8);
            int r = idx >> 2, g = idx & 3;
            cp16(sB + r * 16 + ((g << 2) ^ gsw(r)),
                 W + (size_t)(bn + r) * C_DIM + k0 + g * 8);
        }
        CP_COMMIT();
    };

    load_tile(0, 0);

    for (int it = 0; it < 32; it++) {
        CP_WAIT0();
        __syncthreads();
        const unsigned* cA = smg + (it & 1) * GH_STAGE;
        const unsigned* cB = cA + 4096;
        if (it < 31) load_tile((it + 1) << 5, (it + 1) & 1);

#pragma unroll
        for (int kb = 0; kb < 2; kb++) {
            unsigned af[4][4];
#pragma unroll
            for (int mf = 0; mf < 4; mf++) {
                int row = (wm << 6) + (mf << 4) + ((grp & 1) << 3) + l;
                int colw = (kb << 3) + ((grp >> 1) << 2);
                ldsm4(af[mf], cA + row * 16 + (colw ^ gsw(row)));
            }
            unsigned bf[8][2];
#pragma unroll
            for (int j = 0; j < 4; j++) {
                int row = (wn << 6) + (j << 4) + ((grp >> 1) << 3) + l;
                int colw = (kb << 3) + ((grp & 1) << 2);
                unsigned r4[4];
                ldsm4(r4, cB + row * 16 + (colw ^ gsw(row)));
                bf[2 * j][0] = r4[0];     bf[2 * j][1] = r4[1];
                bf[2 * j + 1][0] = r4[2]; bf[2 * j + 1][1] = r4[3];
            }
#pragma unroll
            for (int nf = 0; nf < 8; nf++)
#pragma unroll
                for (int mf = 0; mf < 4; mf++)
                    mma_f16(acc[mf][nf], af[mf][0], af[mf][1], af[mf][2], af[mf][3],
                            bf[nf][0], bf[nf][1]);
        }
    }

#pragma unroll
    for (int mf = 0; mf < 4; mf++) {
        int gr = bm + (wm << 6) + (mf << 4) + qd;
#pragma unroll
        for (int nf = 0; nf < 8; nf++) {
            int gc = bn + (wn << 6) + (nf << 3) + (u << 1);
            float2 bz = *(const float2*)(bias + gc);
            unsigned o0 = packh2((acc[mf][nf][0] + bz.x) * qscale,
                                 (acc[mf][nf][1] + bz.y) * qscale);
            unsigned o1 = packh2((acc[mf][nf][2] + bz.x) * qscale,
                                 (acc[mf][nf][3] + bz.y) * qscale);
            *(unsigned*)(out + (size_t)gr * C_DIM + gc)       = o0;
            *(unsigned*)(out + (size_t)(gr + 8) * C_DIM + gc) = o1;
        }
    }
}

// ---------------------------------------------------------------------------
// fp16 flash attention, base-2 online softmax. 4 warps x 32 q-rows, chunk 64,
// P in registers; K/V double-buffered cp.async; one __syncthreads per chunk.
// ---------------------------------------------------------------------------
#define AT_Q   0
#define AT_K   4096
#define AT_V   8192
#define AT_M   12288
#define AT_WORDS 12416

__global__ __launch_bounds__(128, 3)
void attn_h(const __half* __restrict__ qg,
            const __half* __restrict__ kg,
            const __half* __restrict__ vg,
            const bool*  __restrict__ maskg,
            float* __restrict__ outg) {
    extern __shared__ unsigned sm[];
    unsigned* Qs = sm + AT_Q;
    unsigned* Kd[2] = { sm + AT_K, sm + AT_K + 2048 };
    unsigned* Vd[2] = { sm + AT_V, sm + AT_V + 2048 };
    float*    msk[2] = { (float*)(sm + AT_M), (float*)(sm + AT_M) + 64 };

    const int tid  = threadIdx.x;
    const int lane = tid & 31;
    const int w    = tid >> 5;
    const int u    = lane & 3;
    const int qd   = lane >> 2;
    const int l    = lane & 7;
    const int grp  = lane >> 3;
    const int b    = blockIdx.z;
    const int h    = blockIdx.y;
    const int t0   = blockIdx.x << 7;
    const int R0   = w << 5;

    const __half* qb = qg + ((size_t)b * T_DIM + t0) * C_DIM + h * D_DIM;
    const __half* kb = kg + (size_t)b * S_DIM * C_DIM + h * D_DIM;
    const __half* vb = vg + (size_t)b * S_DIM * C_DIM + h * D_DIM;
    const bool*  mb = maskg + (size_t)b * S_DIM;

    auto load_kv = [&](int chunk, int buf) {
        const __half* ks = kb + ((size_t)chunk << 6) * C_DIM;
        const __half* vs = vb + ((size_t)chunk << 6) * C_DIM;
#pragma unroll
        for (int i = 0; i < 4; i++) {
            int idx = tid + (i << 7);
            int r = idx >> 3, seg = idx & 7;
            int word = r * 32 + ((seg << 2) ^ ((r & 7) << 2));
            cp16(Kd[buf] + word, ks + (size_t)r * C_DIM + (seg << 3));
            cp16(Vd[buf] + word, vs + (size_t)r * C_DIM + (seg << 3));
        }
        CP_COMMIT();
    };

    // prologue: Q + chunk0 in one group; mask for chunk0
    {
#pragma unroll
        for (int i = 0; i < 8; i++) {
            int idx = tid + (i << 7);
            int r = idx >> 3, seg = idx & 7;
            int word = r * 32 + ((seg << 2) ^ ((r & 7) << 2));
            cp16(Qs + word, qb + (size_t)r * C_DIM + (seg << 3));
        }
#pragma unroll
        for (int i = 0; i < 4; i++) {
            int idx = tid + (i << 7);
            int r = idx >> 3, seg = idx & 7;
            int word = r * 32 + ((seg << 2) ^ ((r & 7) << 2));
            cp16(Kd[0] + word, kb + (size_t)r * C_DIM + (seg << 3));
            cp16(Vd[0] + word, vb + (size_t)r * C_DIM + (seg << 3));
        }
        CP_COMMIT();
        if (tid < 64) msk[0][tid] = mb[tid] ? -1e30f : 0.f;
    }

    float m_i[2][2], l_i[2][2], oacc[2][8][4];
#pragma unroll
    for (int mf = 0; mf < 2; mf++) {
        m_i[mf][0] = -1e30f; m_i[mf][1] = -1e30f;
        l_i[mf][0] = 0.f;    l_i[mf][1] = 0.f;
#pragma unroll
        for (int df = 0; df < 8; df++)
#pragma unroll
            for (int e = 0; e < 4; e++) oacc[mf][df][e] = 0.f;
    }

    const int NCH = S_DIM / 64;
#pragma unroll 1
    for (int i = 0; i < NCH; i++) {
        CP_WAIT0();
        __syncthreads();
        const int buf = i & 1;
        const unsigned* K = Kd[buf];
        const unsigned* V = Vd[buf];
        const float* mk = msk[buf];

        if (i + 1 < NCH) {
            load_kv(i + 1, buf ^ 1);
            if (tid < 64) msk[buf ^ 1][tid] = mb[((i + 1) << 6) + tid] ? -1e30f : 0.f;
        }

        // ---- S = Q K^T  (scores already in log2 domain via q scale) ----
        float sc[2][8][4];
#pragma unroll
        for (int mf = 0; mf < 2; mf++)
#pragma unroll
            for (int nf = 0; nf < 8; nf++)
#pragma unroll
                for (int e = 0; e < 4; e++) sc[mf][nf][e] = 0.f;

#pragma unroll
        for (int kbk = 0; kbk < 4; kbk++) {
            unsigned bkf[8][2];
#pragma unroll
            for (int j = 0; j < 4; j++) {
                int row = (j << 4) + ((grp >> 1) << 3) + l;
                int colw = (kbk << 3) + ((grp & 1) << 2);
                unsigned r4[4];
                ldsm4(r4, K + row * 32 + (colw ^ ((row & 7) << 2)));
                bkf[2 * j][0] = r4[0];     bkf[2 * j][1] = r4[1];
                bkf[2 * j + 1][0] = r4[2]; bkf[2 * j + 1][1] = r4[3];
            }
#pragma unroll
            for (int mf = 0; mf < 2; mf++) {
                int row = R0 + (mf << 4) + ((grp & 1) << 3) + l;
                int colw = (kbk << 3) + ((grp >> 1) << 2);
                unsigned a4[4];
                ldsm4(a4, Qs + row * 32 + (colw ^ ((row & 7) << 2)));
#pragma unroll
                for (int nf = 0; nf < 8; nf++)
                    mma_f16(sc[mf][nf], a4[0], a4[1], a4[2], a4[3],
                            bkf[nf][0], bkf[nf][1]);
            }
        }

        // mask bias
#pragma unroll
        for (int nf = 0; nf < 8; nf++) {
            float bm0 = mk[(nf << 3) + (u << 1)];
            float bm1 = mk[(nf << 3) + (u << 1) + 1];
#pragma unroll
            for (int mf = 0; mf < 2; mf++) {
                sc[mf][nf][0] += bm0; sc[mf][nf][1] += bm1;
                sc[mf][nf][2] += bm0; sc[mf][nf][3] += bm1;
            }
        }

        // ---- base-2 online softmax ----
#pragma unroll
        for (int mf = 0; mf < 2; mf++) {
            float mx0 = -1e30f, mx1 = -1e30f;
#pragma unroll
            for (int nf = 0; nf < 8; nf++) {
                mx0 = fmaxf(mx0, fmaxf(sc[mf][nf][0], sc[mf][nf][1]));
                mx1 = fmaxf(mx1, fmaxf(sc[mf][nf][2], sc[mf][nf][3]));
            }
            mx0 = fmaxf(mx0, __shfl_xor_sync(0xffffffffu, mx0, 1));
            mx0 = fmaxf(mx0, __shfl_xor_sync(0xffffffffu, mx0, 2));
            mx1 = fmaxf(mx1, __shfl_xor_sync(0xffffffffu, mx1, 1));
            mx1 = fmaxf(mx1, __shfl_xor_sync(0xffffffffu, mx1, 2));
            float mn0 = fmaxf(m_i[mf][0], mx0), mn1 = fmaxf(m_i[mf][1], mx1);
            float cr0 = exp2f(m_i[mf][0] - mn0), cr1 = exp2f(m_i[mf][1] - mn1);
            m_i[mf][0] = mn0; m_i[mf][1] = mn1;
            float s0s = 0.f, s1s = 0.f;
#pragma unroll
            for (int nf = 0; nf < 8; nf++) {
                float p0 = exp2f(sc[mf][nf][0] - mn0);
                float p1 = exp2f(sc[mf][nf][1] - mn0);
                float p2 = exp2f(sc[mf][nf][2] - mn1);
                float p3 = exp2f(sc[mf][nf][3] - mn1);
                sc[mf][nf][0] = p0; sc[mf][nf][1] = p1;
                sc[mf][nf][2] = p2; sc[mf][nf][3] = p3;
                s0s += p0 + p1; s1s += p2 + p3;
            }
            s0s += __shfl_xor_sync(0xffffffffu, s0s, 1);
            s0s += __shfl_xor_sync(0xffffffffu, s0s, 2);
            s1s += __shfl_xor_sync(0xffffffffu, s1s, 1);
            s1s += __shfl_xor_sync(0xffffffffu, s1s, 2);
            l_i[mf][0] = l_i[mf][0] * cr0 + s0s;
            l_i[mf][1] = l_i[mf][1] * cr1 + s1s;
#pragma unroll
            for (int df = 0; df < 8; df++) {
                oacc[mf][df][0] *= cr0; oacc[mf][df][1] *= cr0;
                oacc[mf][df][2] *= cr1; oacc[mf][df][3] *= cr1;
            }
        }

        // ---- O += P V  (P from registers; V via ldmatrix.trans) ----
#pragma unroll
        for (int ks = 0; ks < 4; ks++) {
            unsigned bv[8][2];
#pragma unroll
            for (int dfp = 0; dfp < 4; dfp++) {
                int row = (ks << 4) + ((grp & 1) << 3) + l;
                int colw = (dfp << 3) + ((grp >> 1) << 2);
                unsigned r4[4];
                ldsm4t(r4, V + row * 32 + (colw ^ ((row & 7) << 2)));
                bv[2 * dfp][0] = r4[0];     bv[2 * dfp][1] = r4[1];
                bv[2 * dfp + 1][0] = r4[2]; bv[2 * dfp + 1][1] = r4[3];
            }
#pragma unroll
            for (int mf = 0; mf < 2; mf++) {
                unsigned a0 = packh2(sc[mf][2 * ks][0], sc[mf][2 * ks][1]);
                unsigned a1 = packh2(sc[mf][2 * ks][2], sc[mf][2 * ks][3]);
                unsigned a2 = packh2(sc[mf][2 * ks + 1][0], sc[mf][2 * ks + 1][1]);
                unsigned a3 = packh2(sc[mf][2 * ks + 1][2], sc[mf][2 * ks + 1][3]);
#pragma unroll
                for (int df = 0; df < 8; df++)
                    mma_f16(oacc[mf][df], a0, a1, a2, a3, bv[df][0], bv[df][1]);
            }
        }
    }

    // finalize
#pragma unroll
    for (int mf = 0; mf < 2; mf++) {
        float inv0 = 1.0f / l_i[mf][0];
        float inv1 = 1.0f / l_i[mf][1];
        int gr = t0 + R0 + (mf << 4) + qd;
#pragma unroll
        for (int df = 0; df < 8; df++) {
            int gc = h * D_DIM + (df << 3) + (u << 1);
            float2 o0 = make_float2(oacc[mf][df][0] * inv0, oacc[mf][df][1] * inv0);
            float2 o1 = make_float2(oacc[mf][df][2] * inv1, oacc[mf][df][3] * inv1);
            *(float2*)(outg + ((size_t)b * T_DIM + gr) * C_DIM + gc)     = o0;
            *(float2*)(outg + ((size_t)b * T_DIM + gr + 8) * C_DIM + gc) = o1;
        }
    }
}

extern "C" void kernel_launch(void* const* d_in, const int* in_sizes, int n_in,
                              void* d_out, int out_size) {
    const float* query = (const float*)d_in[0];
    const float* key   = (const float*)d_in[1];
    const float* value = (const float*)d_in[2];
    const bool*  kmask = (const bool*)d_in[3];
    const float* Wq = (const float*)d_in[4];
    const float* bq = (const float*)d_in[5];
    const float* Wk = (const float*)d_in[6];
    const float* bk = (const float*)d_in[7];
    const float* Wv = (const float*)d_in[8];
    const float* bv = (const float*)d_in[9];
    float* out = (float*)d_out;

    __half *qp, *kp, *vp, *xq, *xk, *xv, *wq, *wk, *wv;
    cudaGetSymbolAddress((void**)&qp, g_q);
    cudaGetSymbolAddress((void**)&kp, g_k);
    cudaGetSymbolAddress((void**)&vp, g_v);
    cudaGetSymbolAddress((void**)&xq, g_xq);
    cudaGetSymbolAddress((void**)&xk, g_xk);
    cudaGetSymbolAddress((void**)&xv, g_xv);
    cudaGetSymbolAddress((void**)&wq, g_wq);
    cudaGetSymbolAddress((void**)&wk, g_wk);
    cudaGetSymbolAddress((void**)&wv, g_wv);

    static int attr_set = 0;
    if (!attr_set) {
        cudaFuncSetAttribute(qkv_gemm_h, cudaFuncAttributeMaxDynamicSharedMemorySize,
                             2 * GH_STAGE * sizeof(unsigned));
        cudaFuncSetAttribute(attn_h, cudaFuncAttributeMaxDynamicSharedMemorySize,
                             AT_WORDS * sizeof(unsigned));
        attr_set = 1;
    }

    CvtJobs jobs;
    jobs.s[0] = (const float4*)query; jobs.d[0] = (uint2*)xq; jobs.n4[0] = (int)(ACT_N / 4);
    jobs.s[1] = (const float4*)key;   jobs.d[1] = (uint2*)xk; jobs.n4[1] = (int)(ACT_N / 4);
    jobs.s[2] = (const float4*)value; jobs.d[2] = (uint2*)xv; jobs.n4[2] = (int)(ACT_N / 4);
    jobs.s[3] = (const float4*)Wq;    jobs.d[3] = (uint2*)wq; jobs.n4[3] = C_DIM * C_DIM / 4;
    jobs.s[4] = (const float4*)Wk;    jobs.d[4] = (uint2*)wk; jobs.n4[4] = C_DIM * C_DIM / 4;
    jobs.s[5] = (const float4*)Wv;    jobs.d[5] = (uint2*)wv; jobs.n4[5] = C_DIM * C_DIM / 4;
    cvt_all_kernel<<<1184, 256>>>(jobs);

    dim3 gg(C_DIM / 128, (B_DIM * T_DIM) / 256, 3);   // (8, 32, 3)
    qkv_gemm_h<<<gg, 256, 2 * GH_STAGE * sizeof(unsigned)>>>(
        xq, xk, xv, wq, bq, wk, bk, wv, bv, qp, kp, vp);

    dim3 ga(T_DIM / 128, H_DIM, B_DIM);               // (16, 16, 4)
    attn_h<<<ga, 128, AT_WORDS * sizeof(unsigned)>>>(qp, kp, vp, kmask, out);
}